// round 12
// baseline (speedup 1.0000x reference)
#include <cuda_runtime.h>
#include <cuda_fp16.h>
#include <cstdint>

// ===========================================================================
// GraphConvLayer via warp-level mma.sync (m16n8k16 fp16, fp32 accum).
// v6: dst-factored edge MLP. P[n] = nf[n]@W1a + b1 precomputed (fp32, exact-ish);
//     edge GEMM1 only does ef@W1b (K=64) and adds P[dst] in the epilogue.
//     Fragment permutation on W1a/W1b rows makes P/H accesses contiguous.
// ===========================================================================

#define MAX_N 50000
#define MAX_E 800000

__device__ float  g_agg[(size_t)MAX_N * 128];
__device__ float  g_P[(size_t)MAX_N * 128];
__device__ int    g_src[MAX_E];
__device__ int    g_dst[MAX_E];
__device__ __half g_nfh[(size_t)MAX_N * 128];
__device__ __half g_nfl[(size_t)MAX_N * 128];
// weight images (halves):
//  W1Ma hi (perm rows, 128x136)      @0      17408
//  W1Mb hi (perm rows, 128x72)       @17408   9216
//  W2M  hi (perm rows, 128x136)      @26624  17408
//  W1U  hi (128x264)                 @44032  33792
//  W2U  hi (perm rows, 128x136)      @77824  17408
//  W2U  lo (perm rows, 128x136)      @95232  17408
__device__ __half g_wimg[112640];

#define HW_W1MA 0
#define HW_W1MB 17408
#define HW_W2M  26624
#define HW_W1U  44032
#define HW_W2UH 77824
#define HW_W2UL 95232
// byte offsets
#define BW_W1MA 0
#define BW_W1MB 34816
#define BW_W2M  53248
#define BW_W1U  88064
#define BW_W2U  155648   // hi+lo contiguous 69632

// ---------------- helpers ----------------
__device__ __forceinline__ uint32_t smem_u32(const void* p) {
    uint32_t a;
    asm("{ .reg .u64 t; cvta.to.shared.u64 t, %1; cvt.u32.u64 %0, t; }" : "=r"(a) : "l"(p));
    return a;
}
__device__ __forceinline__ float lrelu(float v) { return v >= 0.f ? v : 0.2f * v; }
__device__ __forceinline__ uint32_t packh2(__half a, __half b) {
    __half2 h = __halves2half2(a, b);
    return *reinterpret_cast<uint32_t*>(&h);
}
__device__ __forceinline__ void ldsm4(uint32_t* r, uint32_t a) {
    asm volatile("ldmatrix.sync.aligned.m8n8.x4.shared.b16 {%0,%1,%2,%3}, [%4];"
        : "=r"(r[0]), "=r"(r[1]), "=r"(r[2]), "=r"(r[3]) : "r"(a));
}
__device__ __forceinline__ void mma16816(float* c, const uint32_t* a, uint32_t b0, uint32_t b1) {
    asm volatile("mma.sync.aligned.m16n8k16.row.col.f32.f16.f16.f32 "
        "{%0,%1,%2,%3}, {%4,%5,%6,%7}, {%8,%9}, {%0,%1,%2,%3};"
        : "+f"(c[0]), "+f"(c[1]), "+f"(c[2]), "+f"(c[3])
        : "r"(a[0]), "r"(a[1]), "r"(a[2]), "r"(a[3]), "r"(b0), "r"(b1));
}
__device__ __forceinline__ void red_add_v4(float* p, float a, float b, float c, float d) {
    asm volatile("red.global.add.v4.f32 [%0], {%1, %2, %3, %4};"
        :: "l"(p), "f"(a), "f"(b), "f"(c), "f"(d) : "memory");
}
__device__ __forceinline__ void cp16(uint32_t d, const void* s) {
    asm volatile("cp.async.cg.shared.global [%0], [%1], 16;" :: "r"(d), "l"(s));
}
#define CP_COMMIT() asm volatile("cp.async.commit_group;" ::: "memory")
#define CP_WAIT0()  asm volatile("cp.async.wait_group 0;"  ::: "memory")

// fragment permutation (logical col n -> physical B-image row)
__device__ __host__ __forceinline__ int fperm(int n) {
    int wg = n >> 5, w = n & 31, q = w >> 3, tt = (w >> 1) & 3, r = w & 1;
    return wg * 32 + tt * 8 + q * 2 + r;
}

// 1-term k16 step: c += Ah*Bh.
template<int AS, int BS>
__device__ __forceinline__ void gemm_step1(float (&c)[2][4][4],
    uint32_t aHi, uint32_t bHi, int akb, int bkb, int wm, int wn, int lane)
{
    const int rs = lane & 15;
    const int hs = (lane >> 4) << 4;
    uint32_t ah[2][4], bh[2][4];
    #pragma unroll
    for (int mt = 0; mt < 2; ++mt)
        ldsm4(ah[mt], aHi + (wm * 32 + mt * 16 + rs) * AS + akb + hs);
    #pragma unroll
    for (int nt = 0; nt < 2; ++nt)
        ldsm4(bh[nt], bHi + (wn * 32 + nt * 16 + rs) * BS + bkb + hs);
    #pragma unroll
    for (int mt = 0; mt < 2; ++mt)
        #pragma unroll
        for (int nt = 0; nt < 2; ++nt) {
            mma16816(c[mt][2 * nt],     ah[mt], bh[nt][0], bh[nt][2]);
            mma16816(c[mt][2 * nt + 1], ah[mt], bh[nt][1], bh[nt][3]);
        }
}

// 2-term A-exact: c += Ah*Bh + Al*Bh (weights hi only).
template<int AS, int BS>
__device__ __forceinline__ void gemm_stepA2(float (&c)[2][4][4],
    uint32_t aHi, uint32_t aLo, uint32_t bHi,
    int akb, int bkb, int wm, int wn, int lane)
{
    const int rs = lane & 15;
    const int hs = (lane >> 4) << 4;
    uint32_t ah[2][4], al[2][4], bh[2][4];
    #pragma unroll
    for (int mt = 0; mt < 2; ++mt) {
        ldsm4(ah[mt], aHi + (wm * 32 + mt * 16 + rs) * AS + akb + hs);
        ldsm4(al[mt], aLo + (wm * 32 + mt * 16 + rs) * AS + akb + hs);
    }
    #pragma unroll
    for (int nt = 0; nt < 2; ++nt)
        ldsm4(bh[nt], bHi + (wn * 32 + nt * 16 + rs) * BS + bkb + hs);
    #pragma unroll
    for (int mt = 0; mt < 2; ++mt)
        #pragma unroll
        for (int nt = 0; nt < 2; ++nt) {
            mma16816(c[mt][2 * nt],     ah[mt], bh[nt][0], bh[nt][2]);
            mma16816(c[mt][2 * nt + 1], ah[mt], bh[nt][1], bh[nt][3]);
            mma16816(c[mt][2 * nt],     al[mt], bh[nt][0], bh[nt][2]);
            mma16816(c[mt][2 * nt + 1], al[mt], bh[nt][1], bh[nt][3]);
        }
}

// 3-term: c += Ah*Bh + Ah*Bl + Al*Bh.
template<int AS, int BS>
__device__ __forceinline__ void gemm_step3(float (&c)[2][4][4],
    uint32_t aHi, uint32_t aLo, uint32_t bHi, uint32_t bLo,
    int akb, int bkb, int wm, int wn, int lane)
{
    const int rs = lane & 15;
    const int hs = (lane >> 4) << 4;
    uint32_t ah[2][4], al[2][4], bh[2][4], bl[2][4];
    #pragma unroll
    for (int mt = 0; mt < 2; ++mt) {
        ldsm4(ah[mt], aHi + (wm * 32 + mt * 16 + rs) * AS + akb + hs);
        ldsm4(al[mt], aLo + (wm * 32 + mt * 16 + rs) * AS + akb + hs);
    }
    #pragma unroll
    for (int nt = 0; nt < 2; ++nt) {
        ldsm4(bh[nt], bHi + (wn * 32 + nt * 16 + rs) * BS + bkb + hs);
        ldsm4(bl[nt], bLo + (wn * 32 + nt * 16 + rs) * BS + bkb + hs);
    }
    #pragma unroll
    for (int mt = 0; mt < 2; ++mt)
        #pragma unroll
        for (int nt = 0; nt < 2; ++nt) {
            mma16816(c[mt][2 * nt],     ah[mt], bh[nt][0], bh[nt][2]);
            mma16816(c[mt][2 * nt + 1], ah[mt], bh[nt][1], bh[nt][3]);
            mma16816(c[mt][2 * nt],     ah[mt], bl[nt][0], bl[nt][2]);
            mma16816(c[mt][2 * nt + 1], ah[mt], bl[nt][1], bl[nt][3]);
            mma16816(c[mt][2 * nt],     al[mt], bh[nt][0], bh[nt][2]);
            mma16816(c[mt][2 * nt + 1], al[mt], bh[nt][1], bh[nt][3]);
        }
}

__device__ __forceinline__ void splitpack8(float4 v0, float4 v1, uint4& hi, uint4& lo) {
    float f[8] = {v0.x, v0.y, v0.z, v0.w, v1.x, v1.y, v1.z, v1.w};
    uint32_t hw[4], lw[4];
    #pragma unroll
    for (int j = 0; j < 4; ++j) {
        __half h0 = __float2half_rn(f[2 * j]), h1 = __float2half_rn(f[2 * j + 1]);
        hw[j] = packh2(h0, h1);
        lw[j] = packh2(__float2half_rn(f[2 * j] - __half2float(h0)),
                       __float2half_rn(f[2 * j + 1] - __half2float(h1)));
    }
    hi = make_uint4(hw[0], hw[1], hw[2], hw[3]);
    lo = make_uint4(lw[0], lw[1], lw[2], lw[3]);
}

// ---------------- merged prologue kernel ----------------
__global__ void prep_kernel(const float* __restrict__ nf,
                            const float* __restrict__ mw1, const float* __restrict__ mw2,
                            const float* __restrict__ uw1, const float* __restrict__ uw2,
                            const void* __restrict__ ei, int N, int E)
{
    const int gs = gridDim.x * blockDim.x;
    const int g0 = blockIdx.x * blockDim.x + threadIdx.x;

    // section 1: weight images
    for (int t = g0; t < 90112; t += gs) {
        int u = t;
        const float* src; int n, k, ks, baseH, strideH, baseL = -1; bool prm;
        if (u < 16384)      { n = u >> 7; k = u & 127; ks = k; src = mw1;
                              baseH = HW_W1MA; strideH = 136; prm = true; }
        else if (u < 24576) { u -= 16384; n = u >> 6; k = u & 63; ks = 128 + k; src = mw1;
                              baseH = HW_W1MB; strideH = 72; prm = true; }
        else if (u < 40960) { u -= 24576; n = u >> 7; k = u & 127; ks = k; src = mw2;
                              baseH = HW_W2M; strideH = 136; prm = true; }
        else if (u < 73728) { u -= 40960; n = u >> 8; k = u & 255; ks = k; src = uw1;
                              baseH = HW_W1U; strideH = 264; prm = false; }
        else                { u -= 73728; n = u >> 7; k = u & 127; ks = k; src = uw2;
                              baseH = HW_W2UH; strideH = 136; prm = true; baseL = HW_W2UL; }
        float v = src[(size_t)ks * 128 + n];
        __half h = __float2half_rn(v);
        int row = prm ? fperm(n) : n;
        g_wimg[baseH + row * strideH + k] = h;
        if (baseL >= 0)
            g_wimg[baseL + row * strideH + k] = __float2half_rn(v - __half2float(h));
    }
    // section 2: node_feats hi/lo images
    for (int i = g0; i < N * 64; i += gs) {
        float2 v = ((const float2*)nf)[i];
        __half h0 = __float2half_rn(v.x), h1 = __float2half_rn(v.y);
        ((uint32_t*)g_nfh)[i] = packh2(h0, h1);
        ((uint32_t*)g_nfl)[i] = packh2(__float2half_rn(v.x - __half2float(h0)),
                                       __float2half_rn(v.y - __half2float(h1)));
    }
    // section 3: edge_index conversion (int64/int32 auto)
    {
        const int* p32 = (const int*)ei;
        int s = 0;
        #pragma unroll
        for (int i = 0; i < 16; ++i) s |= p32[2 * i + 1];
        if (s == 0) {
            const long long* p = (const long long*)ei;
            for (int i = g0; i < E; i += gs) {
                g_src[i] = (int)p[i];
                g_dst[i] = (int)p[(size_t)E + i];
            }
        } else {
            for (int i = g0; i < E; i += gs) {
                g_src[i] = p32[i];
                g_dst[i] = p32[(size_t)E + i];
            }
        }
    }
    // section 4: zero agg
    {
        float4 z = make_float4(0.f, 0.f, 0.f, 0.f);
        for (int i = g0; i < N * 32; i += gs) ((float4*)g_agg)[i] = z;
    }
}

// ---------------- P kernel: P = nf @ W1a + b1 (fp32) ----------------
#define Q_W1  0
#define Q_XH  34816
#define Q_XL  69632
#define Q_B1  104448
#define Q_DYN 104960

__global__ __launch_bounds__(512, 1)
void pmat_kernel(const float* __restrict__ b1g, int N, int nTiles)
{
    extern __shared__ char smx[];
    const uint32_t sb = smem_u32(smx);
    float* sb1 = (float*)(smx + Q_B1);
    const int tid = threadIdx.x, lane = tid & 31, wid = tid >> 5;
    const int wm = wid & 3, wn = wid >> 2;

    if (tid < 128) sb1[tid] = b1g[tid];
    {   // stage W1Ma hi once
        const uint4* s = (const uint4*)((const char*)g_wimg + BW_W1MA);
        uint4* d = (uint4*)(smx + Q_W1);
        for (int i = tid; i < 2176; i += 512) d[i] = s[i];
    }

    for (int tile = blockIdx.x; tile < nTiles; tile += gridDim.x) {
        const int n0 = tile * 128;
        __syncthreads();
        for (int t = tid; t < 128 * 32; t += 512) {
            int row = t >> 5, ch = t & 31;
            int n = n0 + row; if (n >= N) n = N - 1;
            if (ch < 16)
                *(uint4*)(smx + Q_XH + row * 272 + ch * 16) = ((const uint4*)(g_nfh + (size_t)n * 128))[ch];
            else
                *(uint4*)(smx + Q_XL + row * 272 + (ch - 16) * 16) = ((const uint4*)(g_nfl + (size_t)n * 128))[ch - 16];
        }
        __syncthreads();

        float c[2][4][4];
        #pragma unroll
        for (int i = 0; i < 2; ++i)
            #pragma unroll
            for (int j = 0; j < 4; ++j)
                #pragma unroll
                for (int r = 0; r < 4; ++r) c[i][j][r] = 0.f;
        #pragma unroll
        for (int k = 0; k < 8; ++k)
            gemm_stepA2<272, 272>(c, sb + Q_XH, sb + Q_XL, sb + Q_W1,
                                  k * 32, k * 32, wm, wn, lane);

        // store P (+b1) — fragments are 8 contiguous logical cols
        const int q = lane & 3;
        const int Lb = wn * 32 + q * 8;
        float b0 = sb1[Lb],     b1v = sb1[Lb + 1], b2v = sb1[Lb + 2], b3v = sb1[Lb + 3];
        float b4v = sb1[Lb + 4], b5v = sb1[Lb + 5], b6v = sb1[Lb + 6], b7v = sb1[Lb + 7];
        #pragma unroll
        for (int mt = 0; mt < 2; ++mt) {
            int r = wm * 32 + mt * 16 + (lane >> 2);
            int nA = n0 + r, nB = n0 + r + 8;
            if (nA < N) {
                float4* p = (float4*)(g_P + (size_t)nA * 128 + Lb);
                p[0] = make_float4(c[mt][0][0] + b0, c[mt][0][1] + b1v, c[mt][1][0] + b2v, c[mt][1][1] + b3v);
                p[1] = make_float4(c[mt][2][0] + b4v, c[mt][2][1] + b5v, c[mt][3][0] + b6v, c[mt][3][1] + b7v);
            }
            if (nB < N) {
                float4* p = (float4*)(g_P + (size_t)nB * 128 + Lb);
                p[0] = make_float4(c[mt][0][2] + b0, c[mt][0][3] + b1v, c[mt][1][2] + b2v, c[mt][1][3] + b3v);
                p[1] = make_float4(c[mt][2][2] + b4v, c[mt][2][3] + b5v, c[mt][3][2] + b6v, c[mt][3][3] + b7v);
            }
        }
    }
}

// ---------------- edge kernel smem layout (bytes) ----------------
#define E_W1B 0        // W1Mb hi 18432 (stride 144)
#define E_W2  18432    // W2M hi 34816 (stride 272)
#define E_H   53248    // H hi 128x272 = 34816
#define E_X   88064    // X (ef fp16) 128x144 = 18432
#define E_EF  106496   // fp32 ef staging 128x256 = 32768
#define E_SRC 139264   // [2][128] ints
#define E_DST 140288   // [2][128] ints
#define E_SB2 141312
#define E_DYN 141824

__device__ __forceinline__ void issue_gather(char* smx, int tile, int E, int tid,
                                             const float* __restrict__ ef) {
    const uint32_t sf = smem_u32(smx) + E_EF;
    const int e0 = tile * 128;
    #pragma unroll
    for (int j = 0; j < 4; ++j) {
        int t = tid + j * 512;            // 0..2047
        int row = t >> 4, ch = t & 15;
        int e = e0 + row; if (e >= E) e = E - 1;
        cp16(sf + row * 256 + ch * 16, ef + (size_t)e * 64 + ch * 4);
    }
}

__global__ __launch_bounds__(512, 1)
void edge_mma_kernel(const float* __restrict__ edge_feats,
                     const float* __restrict__ b2g, int E, int nTiles)
{
    extern __shared__ char smx[];
    const uint32_t sb = smem_u32(smx);
    int*   s_src = (int*)(smx + E_SRC);
    int*   s_dst = (int*)(smx + E_DST);
    float* sb2   = (float*)(smx + E_SB2);
    const int tid = threadIdx.x, lane = tid & 31, wid = tid >> 5;
    const int wm = wid & 3, wn = wid >> 2;

    if (tid < 128) sb2[tid] = b2g[tid];
    {   // stage W1Mb + W2M once
        const uint4* s1 = (const uint4*)((const char*)g_wimg + BW_W1MB);
        uint4* d1 = (uint4*)(smx + E_W1B);
        for (int i = tid; i < 1152; i += 512) d1[i] = s1[i];
        const uint4* s2 = (const uint4*)((const char*)g_wimg + BW_W2M);
        uint4* d2 = (uint4*)(smx + E_W2);
        for (int i = tid; i < 2176; i += 512) d2[i] = s2[i];
    }

    int tile = blockIdx.x;
    if (tile < nTiles) {
        issue_gather(smx, tile, E, tid, edge_feats);
        if (tid < 128) {
            int e = tile * 128 + tid;
            s_src[tid] = (e < E) ? g_src[e] : -1;
            s_dst[tid] = g_dst[(e < E) ? e : (E - 1)];
        }
    }
    CP_COMMIT();

    int b = 0;
    for (; tile < nTiles; tile += gridDim.x, b ^= 1) {
        CP_WAIT0();
        __syncthreads();     // staging + src/dst[b] ready; prev tile fully done

        // convert fp32 staging -> fp16 X (stride 144)
        for (int t = tid; t < 1024; t += 512) {
            int row = t >> 3, q = t & 7;
            const float4* sp = (const float4*)(smx + E_EF + row * 256 + q * 32);
            float4 v0 = sp[0], v1 = sp[1];
            uint32_t w0 = packh2(__float2half_rn(v0.x), __float2half_rn(v0.y));
            uint32_t w1 = packh2(__float2half_rn(v0.z), __float2half_rn(v0.w));
            uint32_t w2 = packh2(__float2half_rn(v1.x), __float2half_rn(v1.y));
            uint32_t w3 = packh2(__float2half_rn(v1.z), __float2half_rn(v1.w));
            *(uint4*)(smx + E_X + row * 144 + q * 16) = make_uint4(w0, w1, w2, w3);
        }
        __syncthreads();     // staging consumed, X built

        int nextTile = tile + gridDim.x;
        if (nextTile < nTiles) {
            issue_gather(smx, nextTile, E, tid, edge_feats);
            if (tid < 128) {
                int e = nextTile * 128 + tid;
                s_src[(b ^ 1) * 128 + tid] = (e < E) ? g_src[e] : -1;
                s_dst[(b ^ 1) * 128 + tid] = g_dst[(e < E) ? e : (E - 1)];
            }
        }
        CP_COMMIT();

        // GEMM1: K=64, 1-term (ef @ W1b)
        float c[2][4][4];
        #pragma unroll
        for (int i = 0; i < 2; ++i)
            #pragma unroll
            for (int j = 0; j < 4; ++j)
                #pragma unroll
                for (int r = 0; r < 4; ++r) c[i][j][r] = 0.f;
        #pragma unroll
        for (int k = 0; k < 4; ++k)
            gemm_step1<144, 144>(c, sb + E_X, sb + E_W1B, k * 32, k * 32, wm, wn, lane);

        // epilogue1: += P[dst] (fp32, L2), lrelu, -> H (logical-order halves)
        {
            const int q = lane & 3;
            const int Lb = wn * 32 + q * 8;
            const int* dp = s_dst + b * 128;
            #pragma unroll
            for (int mt = 0; mt < 2; ++mt) {
                int r = wm * 32 + mt * 16 + (lane >> 2);
                int d0 = dp[r], d1 = dp[r + 8];
                float4 pa0 = ((const float4*)(g_P + (size_t)d0 * 128 + Lb))[0];
                float4 pa1 = ((const float4*)(g_P + (size_t)d0 * 128 + Lb))[1];
                float4 pb0 = ((const float4*)(g_P + (size_t)d1 * 128 + Lb))[0];
                float4 pb1 = ((const float4*)(g_P + (size_t)d1 * 128 + Lb))[1];
                float f0 = lrelu(c[mt][0][0] + pa0.x), f1 = lrelu(c[mt][0][1] + pa0.y);
                float f2 = lrelu(c[mt][1][0] + pa0.z), f3 = lrelu(c[mt][1][1] + pa0.w);
                float f4 = lrelu(c[mt][2][0] + pa1.x), f5 = lrelu(c[mt][2][1] + pa1.y);
                float f6 = lrelu(c[mt][3][0] + pa1.z), f7 = lrelu(c[mt][3][1] + pa1.w);
                *(uint4*)(smx + E_H + r * 272 + Lb * 2) = make_uint4(
                    packh2(__float2half_rn(f0), __float2half_rn(f1)),
                    packh2(__float2half_rn(f2), __float2half_rn(f3)),
                    packh2(__float2half_rn(f4), __float2half_rn(f5)),
                    packh2(__float2half_rn(f6), __float2half_rn(f7)));
                f0 = lrelu(c[mt][0][2] + pb0.x); f1 = lrelu(c[mt][0][3] + pb0.y);
                f2 = lrelu(c[mt][1][2] + pb0.z); f3 = lrelu(c[mt][1][3] + pb0.w);
                f4 = lrelu(c[mt][2][2] + pb1.x); f5 = lrelu(c[mt][2][3] + pb1.y);
                f6 = lrelu(c[mt][3][2] + pb1.z); f7 = lrelu(c[mt][3][3] + pb1.w);
                *(uint4*)(smx + E_H + (r + 8) * 272 + Lb * 2) = make_uint4(
                    packh2(__float2half_rn(f0), __float2half_rn(f1)),
                    packh2(__float2half_rn(f2), __float2half_rn(f3)),
                    packh2(__float2half_rn(f4), __float2half_rn(f5)),
                    packh2(__float2half_rn(f6), __float2half_rn(f7)));
            }
        }
        __syncthreads();     // H complete

        // GEMM2: K=128, 1-term
        #pragma unroll
        for (int i = 0; i < 2; ++i)
            #pragma unroll
            for (int j = 0; j < 4; ++j)
                #pragma unroll
                for (int r = 0; r < 4; ++r) c[i][j][r] = 0.f;
        #pragma unroll
        for (int k = 0; k < 8; ++k)
            gemm_step1<272, 272>(c, sb + E_H, sb + E_W2, k * 32, k * 32, wm, wn, lane);

        // epilogue2: bias + vector scatter-add
        {
            const int q = lane & 3;
            const int Lb = wn * 32 + q * 8;
            const int* sp = s_src + b * 128;
            float c0 = sb2[Lb],     c1 = sb2[Lb + 1], c2 = sb2[Lb + 2], c3 = sb2[Lb + 3];
            float c4 = sb2[Lb + 4], c5 = sb2[Lb + 5], c6 = sb2[Lb + 6], c7 = sb2[Lb + 7];
            #pragma unroll
            for (int mt = 0; mt < 2; ++mt) {
                int r = wm * 32 + mt * 16 + (lane >> 2);
                int s0 = sp[r], s1 = sp[r + 8];
                if (s0 >= 0) {
                    float* p = g_agg + (size_t)s0 * 128 + Lb;
                    red_add_v4(p,     c[mt][0][0] + c0, c[mt][0][1] + c1, c[mt][1][0] + c2, c[mt][1][1] + c3);
                    red_add_v4(p + 4, c[mt][2][0] + c4, c[mt][2][1] + c5, c[mt][3][0] + c6, c[mt][3][1] + c7);
                }
                if (s1 >= 0) {
                    float* p = g_agg + (size_t)s1 * 128 + Lb;
                    red_add_v4(p,     c[mt][0][2] + c0, c[mt][0][3] + c1, c[mt][1][2] + c2, c[mt][1][3] + c3);
                    red_add_v4(p + 4, c[mt][2][2] + c4, c[mt][2][3] + c5, c[mt][3][2] + c6, c[mt][3][3] + c7);
                }
            }
        }
    }
}

// ---------------- persistent node kernel smem layout (bytes) ----------------
#define P_W1  0        // W1U hi, stride 528, 67584
#define P_W2H 67584    // W2U hi, stride 272, 34816
#define P_W2L 102400   // W2U lo, 34816
#define P_XH  137216   // X hi / H hi, stride 272, 34816
#define P_XL  172032   // X lo / H lo, 34816
#define P_SB1 206848
#define P_SB2 207360
#define P_DYN 207872

__global__ __launch_bounds__(512, 1)
void node_mma_kernel(const float* __restrict__ b1g, const float* __restrict__ b2g,
                     float* __restrict__ out, int N, int nTiles)
{
    extern __shared__ char smx[];
    const uint32_t sb = smem_u32(smx);
    float* sb1 = (float*)(smx + P_SB1);
    float* sb2 = (float*)(smx + P_SB2);
    const int tid = threadIdx.x, lane = tid & 31, wid = tid >> 5;
    const int wm = wid & 3, wn = wid >> 2;

    if (tid < 128)      sb1[tid] = b1g[tid];
    else if (tid < 256) sb2[tid - 128] = b2g[tid - 128];
    {
        const uint4* s1 = (const uint4*)((const char*)g_wimg + BW_W1U);
        uint4* d1 = (uint4*)(smx + P_W1);
        for (int i = tid; i < 4224; i += 512) d1[i] = s1[i];
        const uint4* s2 = (const uint4*)((const char*)g_wimg + BW_W2U);
        uint4* d2 = (uint4*)(smx + P_W2H);
        for (int i = tid; i < 4352; i += 512) d2[i] = s2[i];
    }

    for (int tile = blockIdx.x; tile < nTiles; tile += gridDim.x) {
        const int n0 = tile * 128;
        __syncthreads();

        for (int t = tid; t < 128 * 32; t += 512) {
            int row = t >> 5, ch = t & 31;
            int n = n0 + row; if (n >= N) n = N - 1;
            if (ch < 16)
                *(uint4*)(smx + P_XH + row * 272 + ch * 16) = ((const uint4*)(g_nfh + (size_t)n * 128))[ch];
            else
                *(uint4*)(smx + P_XL + row * 272 + (ch - 16) * 16) = ((const uint4*)(g_nfl + (size_t)n * 128))[ch - 16];
        }
        __syncthreads();

        float c[2][4][4];
        #pragma unroll
        for (int i = 0; i < 2; ++i)
            #pragma unroll
            for (int j = 0; j < 4; ++j)
                #pragma unroll
                for (int r = 0; r < 4; ++r) c[i][j][r] = 0.f;
        #pragma unroll
        for (int k = 0; k < 8; ++k)
            gemm_stepA2<272, 528>(c, sb + P_XH, sb + P_XL, sb + P_W1,
                                  k * 32, k * 32, wm, wn, lane);
        __syncthreads();

        for (int t = tid; t < 128 * 16; t += 512) {
            int row = t >> 4, ch = t & 15;
            int n = n0 + row; if (n >= N) n = N - 1;
            const float4* bp = (const float4*)(g_agg + (size_t)n * 128 + ch * 8);
            uint4 hi, lo;
            splitpack8(bp[0], bp[1], hi, lo);
            *(uint4*)(smx + P_XH + row * 272 + ch * 16) = hi;
            *(uint4*)(smx + P_XL + row * 272 + ch * 16) = lo;
        }
        __syncthreads();
        #pragma unroll
        for (int k = 0; k < 8; ++k)
            gemm_stepA2<272, 528>(c, sb + P_XH, sb + P_XL, sb + P_W1,
                                  k * 32, 256 + k * 32, wm, wn, lane);
        __syncthreads();

        #pragma unroll
        for (int mt = 0; mt < 2; ++mt)
            #pragma unroll
            for (int nt = 0; nt < 4; ++nt) {
                int r0  = wm * 32 + mt * 16 + (lane >> 2);
                int col = wn * 32 + nt * 8 + (lane & 3) * 2;
                float ba = sb1[col], bb = sb1[col + 1];
                float f0 = lrelu(c[mt][nt][0] + ba), f1 = lrelu(c[mt][nt][1] + bb);
                float f2 = lrelu(c[mt][nt][2] + ba), f3 = lrelu(c[mt][nt][3] + bb);
                __half h0 = __float2half_rn(f0), h1 = __float2half_rn(f1);
                __half h2 = __float2half_rn(f2), h3 = __float2half_rn(f3);
                *(uint32_t*)(smx + P_XH + r0 * 272 + col * 2)       = packh2(h0, h1);
                *(uint32_t*)(smx + P_XH + (r0 + 8) * 272 + col * 2) = packh2(h2, h3);
                *(uint32_t*)(smx + P_XL + r0 * 272 + col * 2) =
                    packh2(__float2half_rn(f0 - __half2float(h0)), __float2half_rn(f1 - __half2float(h1)));
                *(uint32_t*)(smx + P_XL + (r0 + 8) * 272 + col * 2) =
                    packh2(__float2half_rn(f2 - __half2float(h2)), __float2half_rn(f3 - __half2float(h3)));
            }
        __syncthreads();

        #pragma unroll
        for (int i = 0; i < 2; ++i)
            #pragma unroll
            for (int j = 0; j < 4; ++j)
                #pragma unroll
                for (int r = 0; r < 4; ++r) c[i][j][r] = 0.f;
        #pragma unroll
        for (int k = 0; k < 8; ++k)
            gemm_step3<272, 272>(c, sb + P_XH, sb + P_XL, sb + P_W2H, sb + P_W2L,
                                 k * 32, k * 32, wm, wn, lane);

        {
            const int q = lane & 3;
            const int Lb = wn * 32 + q * 8;
            float c0 = sb2[Lb],     c1 = sb2[Lb + 1], c2 = sb2[Lb + 2], c3 = sb2[Lb + 3];
            float c4 = sb2[Lb + 4], c5 = sb2[Lb + 5], c6 = sb2[Lb + 6], c7 = sb2[Lb + 7];
            #pragma unroll
            for (int mt = 0; mt < 2; ++mt) {
                int r = wm * 32 + mt * 16 + (lane >> 2);
                int nA = n0 + r, nB = n0 + r + 8;
                if (nA < N) {
                    float4* p = (float4*)(out + (size_t)nA * 128 + Lb);
                    p[0] = make_float4(c[mt][0][0] + c0, c[mt][0][1] + c1, c[mt][1][0] + c2, c[mt][1][1] + c3);
                    p[1] = make_float4(c[mt][2][0] + c4, c[mt][2][1] + c5, c[mt][3][0] + c6, c[mt][3][1] + c7);
                }
                if (nB < N) {
                    float4* p = (float4*)(out + (size_t)nB * 128 + Lb);
                    p[0] = make_float4(c[mt][0][2] + c0, c[mt][0][3] + c1, c[mt][1][2] + c2, c[mt][1][3] + c3);
                    p[1] = make_float4(c[mt][2][2] + c4, c[mt][2][3] + c5, c[mt][3][2] + c6, c[mt][3][3] + c7);
                }
            }
        }
    }
}

// ---------------------------------------------------------------------------

extern "C" void kernel_launch(void* const* d_in, const int* in_sizes, int n_in,
                              void* d_out, int out_size)
{
    const float* node_feats = (const float*)d_in[0];
    const float* edge_feats = (const float*)d_in[1];
    const float* msg_w1     = (const float*)d_in[2];
    const float* msg_b1     = (const float*)d_in[3];
    const float* msg_w2     = (const float*)d_in[4];
    const float* msg_b2     = (const float*)d_in[5];
    const float* upd_w1     = (const float*)d_in[6];
    const float* upd_b1     = (const float*)d_in[7];
    const float* upd_w2     = (const float*)d_in[8];
    const float* upd_b2     = (const float*)d_in[9];
    const void*  edge_index = d_in[10];

    const int N = in_sizes[0] / 128;   // 50000
    const int E = in_sizes[1] / 64;    // 800000
    const int nTiles  = (E + 127) / 128;
    const int nNTiles = (N + 127) / 128;

    cudaFuncSetAttribute(pmat_kernel,     cudaFuncAttributeMaxDynamicSharedMemorySize, Q_DYN);
    cudaFuncSetAttribute(edge_mma_kernel, cudaFuncAttributeMaxDynamicSharedMemorySize, E_DYN);
    cudaFuncSetAttribute(node_mma_kernel, cudaFuncAttributeMaxDynamicSharedMemorySize, P_DYN);

    prep_kernel<<<1024, 256>>>(node_feats, msg_w1, msg_w2,
                               upd_w1, upd_w2, edge_index, N, E);

    pmat_kernel<<<148, 512, Q_DYN>>>(msg_b1, N, nNTiles);

    edge_mma_kernel<<<148, 512, E_DYN>>>(edge_feats, msg_b2, E, nTiles);

    node_mma_kernel<<<148, 512, P_DYN>>>(upd_b1, upd_b2, (float*)d_out, N, nNTiles);
}

// round 13
// speedup vs baseline: 1.4774x; 1.4774x over previous
#include <cuda_runtime.h>
#include <cuda_fp16.h>
#include <cstdint>

// ===========================================================================
// GraphConvLayer via warp-level mma.sync (m16n8k16 fp16, fp32 accum).
// v7: dst-factored edge MLP with PREFETCHED fp16 P tiles.
//     P[n] = nf[n]@W1a + b1 (fp16, pmat kernel). Edge GEMM1 = ef@W1b (K=64);
//     P[dst] rows cp.async'd one tile ahead (double-buffered smem, stride 272)
//     and added in epilogue1 from smem — no exposed L2 latency.
// ===========================================================================

#define MAX_N 50000
#define MAX_E 800000

__device__ float  g_agg[(size_t)MAX_N * 128];
__device__ __half g_Ph[(size_t)MAX_N * 128];
__device__ int    g_src[MAX_E];
__device__ int    g_dst[MAX_E];
__device__ __half g_nfh[(size_t)MAX_N * 128];
__device__ __half g_nfl[(size_t)MAX_N * 128];
// weight images (halves): W1Ma hi(perm,136) W1Mb hi(perm,72) W2M hi(perm,136)
//                         W1U hi(264) W2U hi(perm,136) W2U lo(perm,136)
__device__ __half g_wimg[112640];

#define HW_W1MA 0
#define HW_W1MB 17408
#define HW_W2M  26624
#define HW_W1U  44032
#define HW_W2UH 77824
#define HW_W2UL 95232
// byte offsets
#define BW_W1MA 0
#define BW_W1MB 34816
#define BW_W2M  53248
#define BW_W1U  88064
#define BW_W2U  155648   // hi+lo contiguous 69632

// ---------------- helpers ----------------
__device__ __forceinline__ uint32_t smem_u32(const void* p) {
    uint32_t a;
    asm("{ .reg .u64 t; cvta.to.shared.u64 t, %1; cvt.u32.u64 %0, t; }" : "=r"(a) : "l"(p));
    return a;
}
__device__ __forceinline__ float lrelu(float v) { return v >= 0.f ? v : 0.2f * v; }
__device__ __forceinline__ uint32_t packh2(__half a, __half b) {
    __half2 h = __halves2half2(a, b);
    return *reinterpret_cast<uint32_t*>(&h);
}
__device__ __forceinline__ float2 unp2(uint32_t u) {
    __half2 h = *reinterpret_cast<__half2*>(&u);
    return __half22float2(h);
}
__device__ __forceinline__ void ldsm4(uint32_t* r, uint32_t a) {
    asm volatile("ldmatrix.sync.aligned.m8n8.x4.shared.b16 {%0,%1,%2,%3}, [%4];"
        : "=r"(r[0]), "=r"(r[1]), "=r"(r[2]), "=r"(r[3]) : "r"(a));
}
__device__ __forceinline__ void mma16816(float* c, const uint32_t* a, uint32_t b0, uint32_t b1) {
    asm volatile("mma.sync.aligned.m16n8k16.row.col.f32.f16.f16.f32 "
        "{%0,%1,%2,%3}, {%4,%5,%6,%7}, {%8,%9}, {%0,%1,%2,%3};"
        : "+f"(c[0]), "+f"(c[1]), "+f"(c[2]), "+f"(c[3])
        : "r"(a[0]), "r"(a[1]), "r"(a[2]), "r"(a[3]), "r"(b0), "r"(b1));
}
__device__ __forceinline__ void red_add_v4(float* p, float a, float b, float c, float d) {
    asm volatile("red.global.add.v4.f32 [%0], {%1, %2, %3, %4};"
        :: "l"(p), "f"(a), "f"(b), "f"(c), "f"(d) : "memory");
}
__device__ __forceinline__ void cp16(uint32_t d, const void* s) {
    asm volatile("cp.async.cg.shared.global [%0], [%1], 16;" :: "r"(d), "l"(s));
}
#define CP_COMMIT() asm volatile("cp.async.commit_group;" ::: "memory")
#define CP_WAIT0()  asm volatile("cp.async.wait_group 0;"  ::: "memory")

// fragment permutation (logical col n -> physical B-image row)
__device__ __host__ __forceinline__ int fperm(int n) {
    int wg = n >> 5, w = n & 31, q = w >> 3, tt = (w >> 1) & 3, r = w & 1;
    return wg * 32 + tt * 8 + q * 2 + r;
}

// 1-term k16 step: c += Ah*Bh.
template<int AS, int BS>
__device__ __forceinline__ void gemm_step1(float (&c)[2][4][4],
    uint32_t aHi, uint32_t bHi, int akb, int bkb, int wm, int wn, int lane)
{
    const int rs = lane & 15;
    const int hs = (lane >> 4) << 4;
    uint32_t ah[2][4], bh[2][4];
    #pragma unroll
    for (int mt = 0; mt < 2; ++mt)
        ldsm4(ah[mt], aHi + (wm * 32 + mt * 16 + rs) * AS + akb + hs);
    #pragma unroll
    for (int nt = 0; nt < 2; ++nt)
        ldsm4(bh[nt], bHi + (wn * 32 + nt * 16 + rs) * BS + bkb + hs);
    #pragma unroll
    for (int mt = 0; mt < 2; ++mt)
        #pragma unroll
        for (int nt = 0; nt < 2; ++nt) {
            mma16816(c[mt][2 * nt],     ah[mt], bh[nt][0], bh[nt][2]);
            mma16816(c[mt][2 * nt + 1], ah[mt], bh[nt][1], bh[nt][3]);
        }
}

// 2-term A-exact: c += Ah*Bh + Al*Bh (weights hi only).
template<int AS, int BS>
__device__ __forceinline__ void gemm_stepA2(float (&c)[2][4][4],
    uint32_t aHi, uint32_t aLo, uint32_t bHi,
    int akb, int bkb, int wm, int wn, int lane)
{
    const int rs = lane & 15;
    const int hs = (lane >> 4) << 4;
    uint32_t ah[2][4], al[2][4], bh[2][4];
    #pragma unroll
    for (int mt = 0; mt < 2; ++mt) {
        ldsm4(ah[mt], aHi + (wm * 32 + mt * 16 + rs) * AS + akb + hs);
        ldsm4(al[mt], aLo + (wm * 32 + mt * 16 + rs) * AS + akb + hs);
    }
    #pragma unroll
    for (int nt = 0; nt < 2; ++nt)
        ldsm4(bh[nt], bHi + (wn * 32 + nt * 16 + rs) * BS + bkb + hs);
    #pragma unroll
    for (int mt = 0; mt < 2; ++mt)
        #pragma unroll
        for (int nt = 0; nt < 2; ++nt) {
            mma16816(c[mt][2 * nt],     ah[mt], bh[nt][0], bh[nt][2]);
            mma16816(c[mt][2 * nt + 1], ah[mt], bh[nt][1], bh[nt][3]);
            mma16816(c[mt][2 * nt],     al[mt], bh[nt][0], bh[nt][2]);
            mma16816(c[mt][2 * nt + 1], al[mt], bh[nt][1], bh[nt][3]);
        }
}

// 3-term: c += Ah*Bh + Ah*Bl + Al*Bh.
template<int AS, int BS>
__device__ __forceinline__ void gemm_step3(float (&c)[2][4][4],
    uint32_t aHi, uint32_t aLo, uint32_t bHi, uint32_t bLo,
    int akb, int bkb, int wm, int wn, int lane)
{
    const int rs = lane & 15;
    const int hs = (lane >> 4) << 4;
    uint32_t ah[2][4], al[2][4], bh[2][4], bl[2][4];
    #pragma unroll
    for (int mt = 0; mt < 2; ++mt) {
        ldsm4(ah[mt], aHi + (wm * 32 + mt * 16 + rs) * AS + akb + hs);
        ldsm4(al[mt], aLo + (wm * 32 + mt * 16 + rs) * AS + akb + hs);
    }
    #pragma unroll
    for (int nt = 0; nt < 2; ++nt) {
        ldsm4(bh[nt], bHi + (wn * 32 + nt * 16 + rs) * BS + bkb + hs);
        ldsm4(bl[nt], bLo + (wn * 32 + nt * 16 + rs) * BS + bkb + hs);
    }
    #pragma unroll
    for (int mt = 0; mt < 2; ++mt)
        #pragma unroll
        for (int nt = 0; nt < 2; ++nt) {
            mma16816(c[mt][2 * nt],     ah[mt], bh[nt][0], bh[nt][2]);
            mma16816(c[mt][2 * nt + 1], ah[mt], bh[nt][1], bh[nt][3]);
            mma16816(c[mt][2 * nt],     ah[mt], bl[nt][0], bl[nt][2]);
            mma16816(c[mt][2 * nt + 1], ah[mt], bl[nt][1], bl[nt][3]);
            mma16816(c[mt][2 * nt],     al[mt], bh[nt][0], bh[nt][2]);
            mma16816(c[mt][2 * nt + 1], al[mt], bh[nt][1], bh[nt][3]);
        }
}

__device__ __forceinline__ void splitpack8(float4 v0, float4 v1, uint4& hi, uint4& lo) {
    float f[8] = {v0.x, v0.y, v0.z, v0.w, v1.x, v1.y, v1.z, v1.w};
    uint32_t hw[4], lw[4];
    #pragma unroll
    for (int j = 0; j < 4; ++j) {
        __half h0 = __float2half_rn(f[2 * j]), h1 = __float2half_rn(f[2 * j + 1]);
        hw[j] = packh2(h0, h1);
        lw[j] = packh2(__float2half_rn(f[2 * j] - __half2float(h0)),
                       __float2half_rn(f[2 * j + 1] - __half2float(h1)));
    }
    hi = make_uint4(hw[0], hw[1], hw[2], hw[3]);
    lo = make_uint4(lw[0], lw[1], lw[2], lw[3]);
}

// ---------------- merged prologue kernel ----------------
__global__ void prep_kernel(const float* __restrict__ nf,
                            const float* __restrict__ mw1, const float* __restrict__ mw2,
                            const float* __restrict__ uw1, const float* __restrict__ uw2,
                            const void* __restrict__ ei, int N, int E)
{
    const int gs = gridDim.x * blockDim.x;
    const int g0 = blockIdx.x * blockDim.x + threadIdx.x;

    for (int t = g0; t < 90112; t += gs) {
        int u = t;
        const float* src; int n, k, ks, baseH, strideH, baseL = -1; bool prm;
        if (u < 16384)      { n = u >> 7; k = u & 127; ks = k; src = mw1;
                              baseH = HW_W1MA; strideH = 136; prm = true; }
        else if (u < 24576) { u -= 16384; n = u >> 6; k = u & 63; ks = 128 + k; src = mw1;
                              baseH = HW_W1MB; strideH = 72; prm = true; }
        else if (u < 40960) { u -= 24576; n = u >> 7; k = u & 127; ks = k; src = mw2;
                              baseH = HW_W2M; strideH = 136; prm = true; }
        else if (u < 73728) { u -= 40960; n = u >> 8; k = u & 255; ks = k; src = uw1;
                              baseH = HW_W1U; strideH = 264; prm = false; }
        else                { u -= 73728; n = u >> 7; k = u & 127; ks = k; src = uw2;
                              baseH = HW_W2UH; strideH = 136; prm = true; baseL = HW_W2UL; }
        float v = src[(size_t)ks * 128 + n];
        __half h = __float2half_rn(v);
        int row = prm ? fperm(n) : n;
        g_wimg[baseH + row * strideH + k] = h;
        if (baseL >= 0)
            g_wimg[baseL + row * strideH + k] = __float2half_rn(v - __half2float(h));
    }
    for (int i = g0; i < N * 64; i += gs) {
        float2 v = ((const float2*)nf)[i];
        __half h0 = __float2half_rn(v.x), h1 = __float2half_rn(v.y);
        ((uint32_t*)g_nfh)[i] = packh2(h0, h1);
        ((uint32_t*)g_nfl)[i] = packh2(__float2half_rn(v.x - __half2float(h0)),
                                       __float2half_rn(v.y - __half2float(h1)));
    }
    {
        const int* p32 = (const int*)ei;
        int s = 0;
        #pragma unroll
        for (int i = 0; i < 16; ++i) s |= p32[2 * i + 1];
        if (s == 0) {
            const long long* p = (const long long*)ei;
            for (int i = g0; i < E; i += gs) {
                g_src[i] = (int)p[i];
                g_dst[i] = (int)p[(size_t)E + i];
            }
        } else {
            for (int i = g0; i < E; i += gs) {
                g_src[i] = p32[i];
                g_dst[i] = p32[(size_t)E + i];
            }
        }
    }
    {
        float4 z = make_float4(0.f, 0.f, 0.f, 0.f);
        for (int i = g0; i < N * 32; i += gs) ((float4*)g_agg)[i] = z;
    }
}

// ---------------- P kernel: g_Ph = fp16(nf @ W1a + b1) ----------------
#define Q_W1  0
#define Q_XH  34816
#define Q_XL  69632
#define Q_B1  104448
#define Q_DYN 104960

__global__ __launch_bounds__(512, 1)
void pmat_kernel(const float* __restrict__ b1g, int N, int nTiles)
{
    extern __shared__ char smx[];
    const uint32_t sb = smem_u32(smx);
    float* sb1 = (float*)(smx + Q_B1);
    const int tid = threadIdx.x, lane = tid & 31, wid = tid >> 5;
    const int wm = wid & 3, wn = wid >> 2;

    if (tid < 128) sb1[tid] = b1g[tid];
    {
        const uint4* s = (const uint4*)((const char*)g_wimg + BW_W1MA);
        uint4* d = (uint4*)(smx + Q_W1);
        for (int i = tid; i < 2176; i += 512) d[i] = s[i];
    }

    for (int tile = blockIdx.x; tile < nTiles; tile += gridDim.x) {
        const int n0 = tile * 128;
        __syncthreads();
        for (int t = tid; t < 128 * 32; t += 512) {
            int row = t >> 5, ch = t & 31;
            int n = n0 + row; if (n >= N) n = N - 1;
            if (ch < 16)
                *(uint4*)(smx + Q_XH + row * 272 + ch * 16) = ((const uint4*)(g_nfh + (size_t)n * 128))[ch];
            else
                *(uint4*)(smx + Q_XL + row * 272 + (ch - 16) * 16) = ((const uint4*)(g_nfl + (size_t)n * 128))[ch - 16];
        }
        __syncthreads();

        float c[2][4][4];
        #pragma unroll
        for (int i = 0; i < 2; ++i)
            #pragma unroll
            for (int j = 0; j < 4; ++j)
                #pragma unroll
                for (int r = 0; r < 4; ++r) c[i][j][r] = 0.f;
        #pragma unroll
        for (int k = 0; k < 8; ++k)
            gemm_stepA2<272, 272>(c, sb + Q_XH, sb + Q_XL, sb + Q_W1,
                                  k * 32, k * 32, wm, wn, lane);

        // store P (+b1) as fp16 — 8 contiguous logical cols per thread
        const int q = lane & 3;
        const int Lb = wn * 32 + q * 8;
        float b0 = sb1[Lb],      b1v = sb1[Lb + 1], b2v = sb1[Lb + 2], b3v = sb1[Lb + 3];
        float b4v = sb1[Lb + 4], b5v = sb1[Lb + 5], b6v = sb1[Lb + 6], b7v = sb1[Lb + 7];
        #pragma unroll
        for (int mt = 0; mt < 2; ++mt) {
            int r = wm * 32 + mt * 16 + (lane >> 2);
            int nA = n0 + r, nB = n0 + r + 8;
            if (nA < N) {
                *(uint4*)(g_Ph + (size_t)nA * 128 + Lb) = make_uint4(
                    packh2(__float2half_rn(c[mt][0][0] + b0),  __float2half_rn(c[mt][0][1] + b1v)),
                    packh2(__float2half_rn(c[mt][1][0] + b2v), __float2half_rn(c[mt][1][1] + b3v)),
                    packh2(__float2half_rn(c[mt][2][0] + b4v), __float2half_rn(c[mt][2][1] + b5v)),
                    packh2(__float2half_rn(c[mt][3][0] + b6v), __float2half_rn(c[mt][3][1] + b7v)));
            }
            if (nB < N) {
                *(uint4*)(g_Ph + (size_t)nB * 128 + Lb) = make_uint4(
                    packh2(__float2half_rn(c[mt][0][2] + b0),  __float2half_rn(c[mt][0][3] + b1v)),
                    packh2(__float2half_rn(c[mt][1][2] + b2v), __float2half_rn(c[mt][1][3] + b3v)),
                    packh2(__float2half_rn(c[mt][2][2] + b4v), __float2half_rn(c[mt][2][3] + b5v)),
                    packh2(__float2half_rn(c[mt][3][2] + b6v), __float2half_rn(c[mt][3][3] + b7v)));
            }
        }
    }
}

// ---------------- edge kernel smem layout (bytes) ----------------
#define E_W1B 0        // W1Mb hi 18432 (stride 144)
#define E_W2  18432    // W2M hi 34816 (stride 272)
#define E_H   53248    // H hi 128x272 = 34816
#define E_X   88064    // X (ef fp16) 128x144 = 18432
#define E_EF  106496   // fp32 ef staging 128x256 = 32768
#define E_P0  139264   // P fp16 buf0 128x272 = 34816 (stride 272 vs bank conflicts)
#define E_P1  174080   // P fp16 buf1
#define E_SRC 208896   // [2][128]
#define E_DST 209920   // [2][128]
#define E_SB2 210944
#define E_DYN 211456

__device__ __forceinline__ void issue_gather(char* smx, int buf, int tile, int E, int tid,
                                             const float* __restrict__ ef) {
    const uint32_t sf = smem_u32(smx) + E_EF;
    const uint32_t pb = smem_u32(smx) + (buf ? E_P1 : E_P0);
    const int e0 = tile * 128;
    #pragma unroll
    for (int j = 0; j < 8; ++j) {
        int t = tid + j * 512;            // 0..4095
        int row = t >> 5, ch = t & 31;
        int e = e0 + row; if (e >= E) e = E - 1;
        if (ch < 16) {
            cp16(sf + row * 256 + ch * 16, ef + (size_t)e * 64 + ch * 4);
        } else {
            int dn = g_dst[e];
            cp16(pb + row * 272 + (ch - 16) * 16, g_Ph + (size_t)dn * 128 + (ch - 16) * 8);
        }
    }
}

__global__ __launch_bounds__(512, 1)
void edge_mma_kernel(const float* __restrict__ edge_feats,
                     const float* __restrict__ b2g, int E, int nTiles)
{
    extern __shared__ char smx[];
    const uint32_t sb = smem_u32(smx);
    int*   s_src = (int*)(smx + E_SRC);
    float* sb2   = (float*)(smx + E_SB2);
    const int tid = threadIdx.x, lane = tid & 31, wid = tid >> 5;
    const int wm = wid & 3, wn = wid >> 2;

    if (tid < 128) sb2[tid] = b2g[tid];
    {
        const uint4* s1 = (const uint4*)((const char*)g_wimg + BW_W1MB);
        uint4* d1 = (uint4*)(smx + E_W1B);
        for (int i = tid; i < 1152; i += 512) d1[i] = s1[i];
        const uint4* s2 = (const uint4*)((const char*)g_wimg + BW_W2M);
        uint4* d2 = (uint4*)(smx + E_W2);
        for (int i = tid; i < 2176; i += 512) d2[i] = s2[i];
    }

    int tile = blockIdx.x;
    if (tile < nTiles) {
        issue_gather(smx, 0, tile, E, tid, edge_feats);
        if (tid < 128) {
            int e = tile * 128 + tid;
            s_src[tid] = (e < E) ? g_src[e] : -1;
        }
    }
    CP_COMMIT();

    int b = 0;
    for (; tile < nTiles; tile += gridDim.x, b ^= 1) {
        CP_WAIT0();
        __syncthreads();     // staging + P[b] + s_src[b] ready; prev tile done

        // convert fp32 ef staging -> fp16 X (stride 144)
        for (int t = tid; t < 1024; t += 512) {
            int row = t >> 3, q = t & 7;
            const float4* sp = (const float4*)(smx + E_EF + row * 256 + q * 32);
            float4 v0 = sp[0], v1 = sp[1];
            *(uint4*)(smx + E_X + row * 144 + q * 16) = make_uint4(
                packh2(__float2half_rn(v0.x), __float2half_rn(v0.y)),
                packh2(__float2half_rn(v0.z), __float2half_rn(v0.w)),
                packh2(__float2half_rn(v1.x), __float2half_rn(v1.y)),
                packh2(__float2half_rn(v1.z), __float2half_rn(v1.w)));
        }
        __syncthreads();     // staging consumed, X built

        int nextTile = tile + gridDim.x;
        if (nextTile < nTiles) {
            issue_gather(smx, b ^ 1, nextTile, E, tid, edge_feats);
            if (tid < 128) {
                int e = nextTile * 128 + tid;
                s_src[(b ^ 1) * 128 + tid] = (e < E) ? g_src[e] : -1;
            }
        }
        CP_COMMIT();

        // GEMM1: K=64, 1-term (ef @ W1b)
        float c[2][4][4];
        #pragma unroll
        for (int i = 0; i < 2; ++i)
            #pragma unroll
            for (int j = 0; j < 4; ++j)
                #pragma unroll
                for (int r = 0; r < 4; ++r) c[i][j][r] = 0.f;
        #pragma unroll
        for (int k = 0; k < 4; ++k)
            gemm_step1<144, 144>(c, sb + E_X, sb + E_W1B, k * 32, k * 32, wm, wn, lane);

        // epilogue1: += P[b] from smem, lrelu, -> H (logical-order halves)
        {
            const int q = lane & 3;
            const int Lb = wn * 32 + q * 8;
            char* pbuf = smx + (b ? E_P1 : E_P0);
            #pragma unroll
            for (int mt = 0; mt < 2; ++mt) {
                int r = wm * 32 + mt * 16 + (lane >> 2);
                uint4 pa = *(uint4*)(pbuf + r * 272 + Lb * 2);
                uint4 pbv = *(uint4*)(pbuf + (r + 8) * 272 + Lb * 2);
                float2 a0 = unp2(pa.x), a1 = unp2(pa.y), a2 = unp2(pa.z), a3 = unp2(pa.w);
                float f0 = lrelu(c[mt][0][0] + a0.x), f1 = lrelu(c[mt][0][1] + a0.y);
                float f2 = lrelu(c[mt][1][0] + a1.x), f3 = lrelu(c[mt][1][1] + a1.y);
                float f4 = lrelu(c[mt][2][0] + a2.x), f5 = lrelu(c[mt][2][1] + a2.y);
                float f6 = lrelu(c[mt][3][0] + a3.x), f7 = lrelu(c[mt][3][1] + a3.y);
                *(uint4*)(smx + E_H + r * 272 + Lb * 2) = make_uint4(
                    packh2(__float2half_rn(f0), __float2half_rn(f1)),
                    packh2(__float2half_rn(f2), __float2half_rn(f3)),
                    packh2(__float2half_rn(f4), __float2half_rn(f5)),
                    packh2(__float2half_rn(f6), __float2half_rn(f7)));
                float2 b0 = unp2(pbv.x), b1 = unp2(pbv.y), b2 = unp2(pbv.z), b3 = unp2(pbv.w);
                f0 = lrelu(c[mt][0][2] + b0.x); f1 = lrelu(c[mt][0][3] + b0.y);
                f2 = lrelu(c[mt][1][2] + b1.x); f3 = lrelu(c[mt][1][3] + b1.y);
                f4 = lrelu(c[mt][2][2] + b2.x); f5 = lrelu(c[mt][2][3] + b2.y);
                f6 = lrelu(c[mt][3][2] + b3.x); f7 = lrelu(c[mt][3][3] + b3.y);
                *(uint4*)(smx + E_H + (r + 8) * 272 + Lb * 2) = make_uint4(
                    packh2(__float2half_rn(f0), __float2half_rn(f1)),
                    packh2(__float2half_rn(f2), __float2half_rn(f3)),
                    packh2(__float2half_rn(f4), __float2half_rn(f5)),
                    packh2(__float2half_rn(f6), __float2half_rn(f7)));
            }
        }
        __syncthreads();     // H complete

        // GEMM2: K=128, 1-term
        #pragma unroll
        for (int i = 0; i < 2; ++i)
            #pragma unroll
            for (int j = 0; j < 4; ++j)
                #pragma unroll
                for (int r = 0; r < 4; ++r) c[i][j][r] = 0.f;
        #pragma unroll
        for (int k = 0; k < 8; ++k)
            gemm_step1<272, 272>(c, sb + E_H, sb + E_W2, k * 32, k * 32, wm, wn, lane);

        // epilogue2: bias + vector scatter-add
        {
            const int q = lane & 3;
            const int Lb = wn * 32 + q * 8;
            const int* sp = s_src + b * 128;
            float c0 = sb2[Lb],     c1 = sb2[Lb + 1], c2 = sb2[Lb + 2], c3 = sb2[Lb + 3];
            float c4 = sb2[Lb + 4], c5 = sb2[Lb + 5], c6 = sb2[Lb + 6], c7 = sb2[Lb + 7];
            #pragma unroll
            for (int mt = 0; mt < 2; ++mt) {
                int r = wm * 32 + mt * 16 + (lane >> 2);
                int s0 = sp[r], s1 = sp[r + 8];
                if (s0 >= 0) {
                    float* p = g_agg + (size_t)s0 * 128 + Lb;
                    red_add_v4(p,     c[mt][0][0] + c0, c[mt][0][1] + c1, c[mt][1][0] + c2, c[mt][1][1] + c3);
                    red_add_v4(p + 4, c[mt][2][0] + c4, c[mt][2][1] + c5, c[mt][3][0] + c6, c[mt][3][1] + c7);
                }
                if (s1 >= 0) {
                    float* p = g_agg + (size_t)s1 * 128 + Lb;
                    red_add_v4(p,     c[mt][0][2] + c0, c[mt][0][3] + c1, c[mt][1][2] + c2, c[mt][1][3] + c3);
                    red_add_v4(p + 4, c[mt][2][2] + c4, c[mt][2][3] + c5, c[mt][3][2] + c6, c[mt][3][3] + c7);
                }
            }
        }
    }
}

// ---------------- persistent node kernel smem layout (bytes) ----------------
#define P_W1  0        // W1U hi, stride 528, 67584
#define P_W2H 67584    // W2U hi, stride 272, 34816
#define P_W2L 102400   // W2U lo, 34816
#define P_XH  137216   // X hi / H hi, stride 272, 34816
#define P_XL  172032   // X lo / H lo, 34816
#define P_SB1 206848
#define P_SB2 207360
#define P_DYN 207872

__global__ __launch_bounds__(512, 1)
void node_mma_kernel(const float* __restrict__ b1g, const float* __restrict__ b2g,
                     float* __restrict__ out, int N, int nTiles)
{
    extern __shared__ char smx[];
    const uint32_t sb = smem_u32(smx);
    float* sb1 = (float*)(smx + P_SB1);
    float* sb2 = (float*)(smx + P_SB2);
    const int tid = threadIdx.x, lane = tid & 31, wid = tid >> 5;
    const int wm = wid & 3, wn = wid >> 2;

    if (tid < 128)      sb1[tid] = b1g[tid];
    else if (tid < 256) sb2[tid - 128] = b2g[tid - 128];
    {
        const uint4* s1 = (const uint4*)((const char*)g_wimg + BW_W1U);
        uint4* d1 = (uint4*)(smx + P_W1);
        for (int i = tid; i < 4224; i += 512) d1[i] = s1[i];
        const uint4* s2 = (const uint4*)((const char*)g_wimg + BW_W2U);
        uint4* d2 = (uint4*)(smx + P_W2H);
        for (int i = tid; i < 4352; i += 512) d2[i] = s2[i];
    }

    for (int tile = blockIdx.x; tile < nTiles; tile += gridDim.x) {
        const int n0 = tile * 128;
        __syncthreads();

        for (int t = tid; t < 128 * 32; t += 512) {
            int row = t >> 5, ch = t & 31;
            int n = n0 + row; if (n >= N) n = N - 1;
            if (ch < 16)
                *(uint4*)(smx + P_XH + row * 272 + ch * 16) = ((const uint4*)(g_nfh + (size_t)n * 128))[ch];
            else
                *(uint4*)(smx + P_XL + row * 272 + (ch - 16) * 16) = ((const uint4*)(g_nfl + (size_t)n * 128))[ch - 16];
        }
        __syncthreads();

        float c[2][4][4];
        #pragma unroll
        for (int i = 0; i < 2; ++i)
            #pragma unroll
            for (int j = 0; j < 4; ++j)
                #pragma unroll
                for (int r = 0; r < 4; ++r) c[i][j][r] = 0.f;
        #pragma unroll
        for (int k = 0; k < 8; ++k)
            gemm_stepA2<272, 528>(c, sb + P_XH, sb + P_XL, sb + P_W1,
                                  k * 32, k * 32, wm, wn, lane);
        __syncthreads();

        for (int t = tid; t < 128 * 16; t += 512) {
            int row = t >> 4, ch = t & 15;
            int n = n0 + row; if (n >= N) n = N - 1;
            const float4* bp = (const float4*)(g_agg + (size_t)n * 128 + ch * 8);
            uint4 hi, lo;
            splitpack8(bp[0], bp[1], hi, lo);
            *(uint4*)(smx + P_XH + row * 272 + ch * 16) = hi;
            *(uint4*)(smx + P_XL + row * 272 + ch * 16) = lo;
        }
        __syncthreads();
        #pragma unroll
        for (int k = 0; k < 8; ++k)
            gemm_stepA2<272, 528>(c, sb + P_XH, sb + P_XL, sb + P_W1,
                                  k * 32, 256 + k * 32, wm, wn, lane);
        __syncthreads();

        #pragma unroll
        for (int mt = 0; mt < 2; ++mt)
            #pragma unroll
            for (int nt = 0; nt < 4; ++nt) {
                int r0  = wm * 32 + mt * 16 + (lane >> 2);
                int col = wn * 32 + nt * 8 + (lane & 3) * 2;
                float ba = sb1[col], bb = sb1[col + 1];
                float f0 = lrelu(c[mt][nt][0] + ba), f1 = lrelu(c[mt][nt][1] + bb);
                float f2 = lrelu(c[mt][nt][2] + ba), f3 = lrelu(c[mt][nt][3] + bb);
                __half h0 = __float2half_rn(f0), h1 = __float2half_rn(f1);
                __half h2 = __float2half_rn(f2), h3 = __float2half_rn(f3);
                *(uint32_t*)(smx + P_XH + r0 * 272 + col * 2)       = packh2(h0, h1);
                *(uint32_t*)(smx + P_XH + (r0 + 8) * 272 + col * 2) = packh2(h2, h3);
                *(uint32_t*)(smx + P_XL + r0 * 272 + col * 2) =
                    packh2(__float2half_rn(f0 - __half2float(h0)), __float2half_rn(f1 - __half2float(h1)));
                *(uint32_t*)(smx + P_XL + (r0 + 8) * 272 + col * 2) =
                    packh2(__float2half_rn(f2 - __half2float(h2)), __float2half_rn(f3 - __half2float(h3)));
            }
        __syncthreads();

        #pragma unroll
        for (int i = 0; i < 2; ++i)
            #pragma unroll
            for (int j = 0; j < 4; ++j)
                #pragma unroll
                for (int r = 0; r < 4; ++r) c[i][j][r] = 0.f;
        #pragma unroll
        for (int k = 0; k < 8; ++k)
            gemm_step3<272, 272>(c, sb + P_XH, sb + P_XL, sb + P_W2H, sb + P_W2L,
                                 k * 32, k * 32, wm, wn, lane);

        {
            const int q = lane & 3;
            const int Lb = wn * 32 + q * 8;
            float c0 = sb2[Lb],     c1 = sb2[Lb + 1], c2 = sb2[Lb + 2], c3 = sb2[Lb + 3];
            float c4 = sb2[Lb + 4], c5 = sb2[Lb + 5], c6 = sb2[Lb + 6], c7 = sb2[Lb + 7];
            #pragma unroll
            for (int mt = 0; mt < 2; ++mt) {
                int r = wm * 32 + mt * 16 + (lane >> 2);
                int nA = n0 + r, nB = n0 + r + 8;
                if (nA < N) {
                    float4* p = (float4*)(out + (size_t)nA * 128 + Lb);
                    p[0] = make_float4(c[mt][0][0] + c0, c[mt][0][1] + c1, c[mt][1][0] + c2, c[mt][1][1] + c3);
                    p[1] = make_float4(c[mt][2][0] + c4, c[mt][2][1] + c5, c[mt][3][0] + c6, c[mt][3][1] + c7);
                }
                if (nB < N) {
                    float4* p = (float4*)(out + (size_t)nB * 128 + Lb);
                    p[0] = make_float4(c[mt][0][2] + c0, c[mt][0][3] + c1, c[mt][1][2] + c2, c[mt][1][3] + c3);
                    p[1] = make_float4(c[mt][2][2] + c4, c[mt][2][3] + c5, c[mt][3][2] + c6, c[mt][3][3] + c7);
                }
            }
        }
    }
}

// ---------------------------------------------------------------------------

extern "C" void kernel_launch(void* const* d_in, const int* in_sizes, int n_in,
                              void* d_out, int out_size)
{
    const float* node_feats = (const float*)d_in[0];
    const float* edge_feats = (const float*)d_in[1];
    const float* msg_w1     = (const float*)d_in[2];
    const float* msg_b1     = (const float*)d_in[3];
    const float* msg_w2     = (const float*)d_in[4];
    const float* msg_b2     = (const float*)d_in[5];
    const float* upd_w1     = (const float*)d_in[6];
    const float* upd_b1     = (const float*)d_in[7];
    const float* upd_w2     = (const float*)d_in[8];
    const float* upd_b2     = (const float*)d_in[9];
    const void*  edge_index = d_in[10];

    const int N = in_sizes[0] / 128;   // 50000
    const int E = in_sizes[1] / 64;    // 800000
    const int nTiles  = (E + 127) / 128;
    const int nNTiles = (N + 127) / 128;

    cudaFuncSetAttribute(pmat_kernel,     cudaFuncAttributeMaxDynamicSharedMemorySize, Q_DYN);
    cudaFuncSetAttribute(edge_mma_kernel, cudaFuncAttributeMaxDynamicSharedMemorySize, E_DYN);
    cudaFuncSetAttribute(node_mma_kernel, cudaFuncAttributeMaxDynamicSharedMemorySize, P_DYN);

    prep_kernel<<<1024, 256>>>(node_feats, msg_w1, msg_w2,
                               upd_w1, upd_w2, edge_index, N, E);

    pmat_kernel<<<148, 512, Q_DYN>>>(msg_b1, N, nNTiles);

    edge_mma_kernel<<<148, 512, E_DYN>>>(edge_feats, msg_b2, E, nTiles);

    node_mma_kernel<<<148, 512, P_DYN>>>(upd_b1, upd_b2, (float*)d_out, N, nNTiles);
}

// round 14
// speedup vs baseline: 1.7811x; 1.2056x over previous
#include <cuda_runtime.h>
#include <cuda_fp16.h>
#include <cstdint>

// ===========================================================================
// GraphConvLayer via warp-level mma.sync (m16n8k16 fp16, fp32 accum).
// v8: linear-scatter factoring. segment_sum(H@W2+b2) = segment_sum(H)@W2+deg*b2,
//     so the edge kernel scatters fp32 H directly (no GEMM2) and the node
//     kernel consumes aggH through the precomputed chain Wc = W2M@W1U[128:256]
//     (+ per-node deg * vc, vc = b2@W1U[128:256]).
// ===========================================================================

#define MAX_N 50000
#define MAX_E 800000

__device__ float  g_agg[(size_t)MAX_N * 128];   // aggregated H (fp32)
__device__ float  g_degf[MAX_N];                // per-node degree (float)
__device__ float  g_vc[128];                    // b2 @ W1U[128:256]
__device__ __half g_Ph[(size_t)MAX_N * 128];
__device__ int    g_src[MAX_E];
__device__ int    g_dst[MAX_E];
__device__ __half g_nfh[(size_t)MAX_N * 128];
__device__ __half g_nfl[(size_t)MAX_N * 128];
// weight images (halves): W1Ma hi(perm,136) W1Mb hi(perm,72) W2M hi(perm,136)
//                         W1U hi(264; k>=128 rows hold Wc) W2U hi/lo(perm,136)
__device__ __half g_wimg[112640];

#define HW_W1MA 0
#define HW_W1MB 17408
#define HW_W2M  26624
#define HW_W1U  44032
#define HW_W2UH 77824
#define HW_W2UL 95232
// byte offsets
#define BW_W1MA 0
#define BW_W1MB 34816
#define BW_W2M  53248
#define BW_W1U  88064
#define BW_W2U  155648

// ---------------- helpers ----------------
__device__ __forceinline__ uint32_t smem_u32(const void* p) {
    uint32_t a;
    asm("{ .reg .u64 t; cvta.to.shared.u64 t, %1; cvt.u32.u64 %0, t; }" : "=r"(a) : "l"(p));
    return a;
}
__device__ __forceinline__ float lrelu(float v) { return v >= 0.f ? v : 0.2f * v; }
__device__ __forceinline__ uint32_t packh2(__half a, __half b) {
    __half2 h = __halves2half2(a, b);
    return *reinterpret_cast<uint32_t*>(&h);
}
__device__ __forceinline__ float2 unp2(uint32_t u) {
    __half2 h = *reinterpret_cast<__half2*>(&u);
    return __half22float2(h);
}
__device__ __forceinline__ void ldsm4(uint32_t* r, uint32_t a) {
    asm volatile("ldmatrix.sync.aligned.m8n8.x4.shared.b16 {%0,%1,%2,%3}, [%4];"
        : "=r"(r[0]), "=r"(r[1]), "=r"(r[2]), "=r"(r[3]) : "r"(a));
}
__device__ __forceinline__ void mma16816(float* c, const uint32_t* a, uint32_t b0, uint32_t b1) {
    asm volatile("mma.sync.aligned.m16n8k16.row.col.f32.f16.f16.f32 "
        "{%0,%1,%2,%3}, {%4,%5,%6,%7}, {%8,%9}, {%0,%1,%2,%3};"
        : "+f"(c[0]), "+f"(c[1]), "+f"(c[2]), "+f"(c[3])
        : "r"(a[0]), "r"(a[1]), "r"(a[2]), "r"(a[3]), "r"(b0), "r"(b1));
}
__device__ __forceinline__ void red_add_v4(float* p, float a, float b, float c, float d) {
    asm volatile("red.global.add.v4.f32 [%0], {%1, %2, %3, %4};"
        :: "l"(p), "f"(a), "f"(b), "f"(c), "f"(d) : "memory");
}
__device__ __forceinline__ void red_add_f(float* p, float v) {
    asm volatile("red.global.add.f32 [%0], %1;" :: "l"(p), "f"(v) : "memory");
}
__device__ __forceinline__ void cp16(uint32_t d, const void* s) {
    asm volatile("cp.async.cg.shared.global [%0], [%1], 16;" :: "r"(d), "l"(s));
}
#define CP_COMMIT() asm volatile("cp.async.commit_group;" ::: "memory")
#define CP_WAIT0()  asm volatile("cp.async.wait_group 0;"  ::: "memory")

// fragment permutation (logical col n -> physical B-image row)
__device__ __host__ __forceinline__ int fperm(int n) {
    int wg = n >> 5, w = n & 31, q = w >> 3, tt = (w >> 1) & 3, r = w & 1;
    return wg * 32 + tt * 8 + q * 2 + r;
}

// 1-term k16 step: c += Ah*Bh.
template<int AS, int BS>
__device__ __forceinline__ void gemm_step1(float (&c)[2][4][4],
    uint32_t aHi, uint32_t bHi, int akb, int bkb, int wm, int wn, int lane)
{
    const int rs = lane & 15;
    const int hs = (lane >> 4) << 4;
    uint32_t ah[2][4], bh[2][4];
    #pragma unroll
    for (int mt = 0; mt < 2; ++mt)
        ldsm4(ah[mt], aHi + (wm * 32 + mt * 16 + rs) * AS + akb + hs);
    #pragma unroll
    for (int nt = 0; nt < 2; ++nt)
        ldsm4(bh[nt], bHi + (wn * 32 + nt * 16 + rs) * BS + bkb + hs);
    #pragma unroll
    for (int mt = 0; mt < 2; ++mt)
        #pragma unroll
        for (int nt = 0; nt < 2; ++nt) {
            mma16816(c[mt][2 * nt],     ah[mt], bh[nt][0], bh[nt][2]);
            mma16816(c[mt][2 * nt + 1], ah[mt], bh[nt][1], bh[nt][3]);
        }
}

// 2-term A-exact: c += Ah*Bh + Al*Bh (weights hi only).
template<int AS, int BS>
__device__ __forceinline__ void gemm_stepA2(float (&c)[2][4][4],
    uint32_t aHi, uint32_t aLo, uint32_t bHi,
    int akb, int bkb, int wm, int wn, int lane)
{
    const int rs = lane & 15;
    const int hs = (lane >> 4) << 4;
    uint32_t ah[2][4], al[2][4], bh[2][4];
    #pragma unroll
    for (int mt = 0; mt < 2; ++mt) {
        ldsm4(ah[mt], aHi + (wm * 32 + mt * 16 + rs) * AS + akb + hs);
        ldsm4(al[mt], aLo + (wm * 32 + mt * 16 + rs) * AS + akb + hs);
    }
    #pragma unroll
    for (int nt = 0; nt < 2; ++nt)
        ldsm4(bh[nt], bHi + (wn * 32 + nt * 16 + rs) * BS + bkb + hs);
    #pragma unroll
    for (int mt = 0; mt < 2; ++mt)
        #pragma unroll
        for (int nt = 0; nt < 2; ++nt) {
            mma16816(c[mt][2 * nt],     ah[mt], bh[nt][0], bh[nt][2]);
            mma16816(c[mt][2 * nt + 1], ah[mt], bh[nt][1], bh[nt][3]);
            mma16816(c[mt][2 * nt],     al[mt], bh[nt][0], bh[nt][2]);
            mma16816(c[mt][2 * nt + 1], al[mt], bh[nt][1], bh[nt][3]);
        }
}

// 3-term: c += Ah*Bh + Ah*Bl + Al*Bh.
template<int AS, int BS>
__device__ __forceinline__ void gemm_step3(float (&c)[2][4][4],
    uint32_t aHi, uint32_t aLo, uint32_t bHi, uint32_t bLo,
    int akb, int bkb, int wm, int wn, int lane)
{
    const int rs = lane & 15;
    const int hs = (lane >> 4) << 4;
    uint32_t ah[2][4], al[2][4], bh[2][4], bl[2][4];
    #pragma unroll
    for (int mt = 0; mt < 2; ++mt) {
        ldsm4(ah[mt], aHi + (wm * 32 + mt * 16 + rs) * AS + akb + hs);
        ldsm4(al[mt], aLo + (wm * 32 + mt * 16 + rs) * AS + akb + hs);
    }
    #pragma unroll
    for (int nt = 0; nt < 2; ++nt) {
        ldsm4(bh[nt], bHi + (wn * 32 + nt * 16 + rs) * BS + bkb + hs);
        ldsm4(bl[nt], bLo + (wn * 32 + nt * 16 + rs) * BS + bkb + hs);
    }
    #pragma unroll
    for (int mt = 0; mt < 2; ++mt)
        #pragma unroll
        for (int nt = 0; nt < 2; ++nt) {
            mma16816(c[mt][2 * nt],     ah[mt], bh[nt][0], bh[nt][2]);
            mma16816(c[mt][2 * nt + 1], ah[mt], bh[nt][1], bh[nt][3]);
            mma16816(c[mt][2 * nt],     ah[mt], bl[nt][0], bl[nt][2]);
            mma16816(c[mt][2 * nt + 1], ah[mt], bl[nt][1], bl[nt][3]);
            mma16816(c[mt][2 * nt],     al[mt], bh[nt][0], bh[nt][2]);
            mma16816(c[mt][2 * nt + 1], al[mt], bh[nt][1], bh[nt][3]);
        }
}

__device__ __forceinline__ void splitpack8(float4 v0, float4 v1, uint4& hi, uint4& lo) {
    float f[8] = {v0.x, v0.y, v0.z, v0.w, v1.x, v1.y, v1.z, v1.w};
    uint32_t hw[4], lw[4];
    #pragma unroll
    for (int j = 0; j < 4; ++j) {
        __half h0 = __float2half_rn(f[2 * j]), h1 = __float2half_rn(f[2 * j + 1]);
        hw[j] = packh2(h0, h1);
        lw[j] = packh2(__float2half_rn(f[2 * j] - __half2float(h0)),
                       __float2half_rn(f[2 * j + 1] - __half2float(h1)));
    }
    hi = make_uint4(hw[0], hw[1], hw[2], hw[3]);
    lo = make_uint4(lw[0], lw[1], lw[2], lw[3]);
}

// ---------------- merged prologue kernel ----------------
__global__ void prep_kernel(const float* __restrict__ nf,
                            const float* __restrict__ mw1, const float* __restrict__ mw2,
                            const float* __restrict__ mb2,
                            const float* __restrict__ uw1, const float* __restrict__ uw2,
                            const void* __restrict__ ei, int N, int E)
{
    const int gs = gridDim.x * blockDim.x;
    const int g0 = blockIdx.x * blockDim.x + threadIdx.x;

    for (int t = g0; t < 90112; t += gs) {
        int u = t;
        if (u < 16384) {                      // W1Ma
            int n = u >> 7, k = u & 127;
            float v = mw1[(size_t)k * 128 + n];
            g_wimg[HW_W1MA + fperm(n) * 136 + k] = __float2half_rn(v);
        } else if (u < 24576) {               // W1Mb
            u -= 16384; int n = u >> 6, k = u & 63;
            float v = mw1[(size_t)(128 + k) * 128 + n];
            g_wimg[HW_W1MB + fperm(n) * 72 + k] = __float2half_rn(v);
        } else if (u < 40960) {               // W2M (unused by edge now; kept harmless)
            u -= 24576; int n = u >> 7, k = u & 127;
            float v = mw2[(size_t)k * 128 + n];
            g_wimg[HW_W2M + fperm(n) * 136 + k] = __float2half_rn(v);
        } else if (u < 73728) {               // W1U rows; k>=128 hold chain Wc
            u -= 40960; int n = u >> 8, k = u & 255;
            float v;
            if (k < 128) {
                v = uw1[(size_t)k * 128 + n];
            } else {
                int kk = k - 128;
                v = 0.f;
                for (int j = 0; j < 128; ++j)
                    v += mw2[(size_t)kk * 128 + j] * uw1[(size_t)(128 + j) * 128 + n];
            }
            g_wimg[HW_W1U + n * 264 + k] = __float2half_rn(v);
        } else {                              // W2U hi+lo
            u -= 73728; int n = u >> 7, k = u & 127;
            float v = uw2[(size_t)k * 128 + n];
            __half h = __float2half_rn(v);
            int row = fperm(n);
            g_wimg[HW_W2UH + row * 136 + k] = h;
            g_wimg[HW_W2UL + row * 136 + k] = __float2half_rn(v - __half2float(h));
        }
    }
    // vc = b2 @ W1U[128:256]
    for (int t = g0; t < 128; t += gs) {
        float v = 0.f;
        for (int j = 0; j < 128; ++j)
            v += mb2[j] * uw1[(size_t)(128 + j) * 128 + t];
        g_vc[t] = v;
    }
    for (int i = g0; i < N * 64; i += gs) {
        float2 v = ((const float2*)nf)[i];
        __half h0 = __float2half_rn(v.x), h1 = __float2half_rn(v.y);
        ((uint32_t*)g_nfh)[i] = packh2(h0, h1);
        ((uint32_t*)g_nfl)[i] = packh2(__float2half_rn(v.x - __half2float(h0)),
                                       __float2half_rn(v.y - __half2float(h1)));
    }
    {
        const int* p32 = (const int*)ei;
        int s = 0;
        #pragma unroll
        for (int i = 0; i < 16; ++i) s |= p32[2 * i + 1];
        if (s == 0) {
            const long long* p = (const long long*)ei;
            for (int i = g0; i < E; i += gs) {
                g_src[i] = (int)p[i];
                g_dst[i] = (int)p[(size_t)E + i];
            }
        } else {
            for (int i = g0; i < E; i += gs) {
                g_src[i] = p32[i];
                g_dst[i] = p32[(size_t)E + i];
            }
        }
    }
    {
        float4 z = make_float4(0.f, 0.f, 0.f, 0.f);
        for (int i = g0; i < N * 32; i += gs) ((float4*)g_agg)[i] = z;
        for (int i = g0; i < N; i += gs) g_degf[i] = 0.f;
    }
}

// ---------------- P kernel: g_Ph = fp16(nf @ W1a + b1) ----------------
#define Q_W1  0
#define Q_XH  34816
#define Q_XL  69632
#define Q_B1  104448
#define Q_DYN 104960

__global__ __launch_bounds__(512, 1)
void pmat_kernel(const float* __restrict__ b1g, int N, int nTiles)
{
    extern __shared__ char smx[];
    const uint32_t sb = smem_u32(smx);
    float* sb1 = (float*)(smx + Q_B1);
    const int tid = threadIdx.x, lane = tid & 31, wid = tid >> 5;
    const int wm = wid & 3, wn = wid >> 2;

    if (tid < 128) sb1[tid] = b1g[tid];
    {
        const uint4* s = (const uint4*)((const char*)g_wimg + BW_W1MA);
        uint4* d = (uint4*)(smx + Q_W1);
        for (int i = tid; i < 2176; i += 512) d[i] = s[i];
    }

    for (int tile = blockIdx.x; tile < nTiles; tile += gridDim.x) {
        const int n0 = tile * 128;
        __syncthreads();
        for (int t = tid; t < 128 * 32; t += 512) {
            int row = t >> 5, ch = t & 31;
            int n = n0 + row; if (n >= N) n = N - 1;
            if (ch < 16)
                *(uint4*)(smx + Q_XH + row * 272 + ch * 16) = ((const uint4*)(g_nfh + (size_t)n * 128))[ch];
            else
                *(uint4*)(smx + Q_XL + row * 272 + (ch - 16) * 16) = ((const uint4*)(g_nfl + (size_t)n * 128))[ch - 16];
        }
        __syncthreads();

        float c[2][4][4];
        #pragma unroll
        for (int i = 0; i < 2; ++i)
            #pragma unroll
            for (int j = 0; j < 4; ++j)
                #pragma unroll
                for (int r = 0; r < 4; ++r) c[i][j][r] = 0.f;
        #pragma unroll
        for (int k = 0; k < 8; ++k)
            gemm_stepA2<272, 272>(c, sb + Q_XH, sb + Q_XL, sb + Q_W1,
                                  k * 32, k * 32, wm, wn, lane);

        const int q = lane & 3;
        const int Lb = wn * 32 + q * 8;
        float b0 = sb1[Lb],      b1v = sb1[Lb + 1], b2v = sb1[Lb + 2], b3v = sb1[Lb + 3];
        float b4v = sb1[Lb + 4], b5v = sb1[Lb + 5], b6v = sb1[Lb + 6], b7v = sb1[Lb + 7];
        #pragma unroll
        for (int mt = 0; mt < 2; ++mt) {
            int r = wm * 32 + mt * 16 + (lane >> 2);
            int nA = n0 + r, nB = n0 + r + 8;
            if (nA < N) {
                *(uint4*)(g_Ph + (size_t)nA * 128 + Lb) = make_uint4(
                    packh2(__float2half_rn(c[mt][0][0] + b0),  __float2half_rn(c[mt][0][1] + b1v)),
                    packh2(__float2half_rn(c[mt][1][0] + b2v), __float2half_rn(c[mt][1][1] + b3v)),
                    packh2(__float2half_rn(c[mt][2][0] + b4v), __float2half_rn(c[mt][2][1] + b5v)),
                    packh2(__float2half_rn(c[mt][3][0] + b6v), __float2half_rn(c[mt][3][1] + b7v)));
            }
            if (nB < N) {
                *(uint4*)(g_Ph + (size_t)nB * 128 + Lb) = make_uint4(
                    packh2(__float2half_rn(c[mt][0][2] + b0),  __float2half_rn(c[mt][0][3] + b1v)),
                    packh2(__float2half_rn(c[mt][1][2] + b2v), __float2half_rn(c[mt][1][3] + b3v)),
                    packh2(__float2half_rn(c[mt][2][2] + b4v), __float2half_rn(c[mt][2][3] + b5v)),
                    packh2(__float2half_rn(c[mt][3][2] + b6v), __float2half_rn(c[mt][3][3] + b7v)));
            }
        }
    }
}

// ---------------- edge kernel smem layout (bytes) ----------------
#define E_W1B 0        // W1Mb hi 18432 (stride 144)
#define E_X   18432    // X (ef fp16) 128x144 = 18432
#define E_EF  36864    // fp32 ef staging 128x256 = 32768
#define E_P0  69632    // P fp16 buf0 128x272 = 34816
#define E_P1  104448   // P fp16 buf1
#define E_SRC 139264   // [2][128]
#define E_DYN 140288

__device__ __forceinline__ void issue_gather(char* smx, int buf, int tile, int E, int tid,
                                             const float* __restrict__ ef) {
    const uint32_t sf = smem_u32(smx) + E_EF;
    const uint32_t pb = smem_u32(smx) + (buf ? E_P1 : E_P0);
    const int e0 = tile * 128;
    #pragma unroll
    for (int j = 0; j < 8; ++j) {
        int t = tid + j * 512;            // 0..4095
        int row = t >> 5, ch = t & 31;
        int e = e0 + row; if (e >= E) e = E - 1;
        if (ch < 16) {
            cp16(sf + row * 256 + ch * 16, ef + (size_t)e * 64 + ch * 4);
        } else {
            int dn = g_dst[e];
            cp16(pb + row * 272 + (ch - 16) * 16, g_Ph + (size_t)dn * 128 + (ch - 16) * 8);
        }
    }
}

__global__ __launch_bounds__(512, 1)
void edge_mma_kernel(const float* __restrict__ edge_feats, int E, int nTiles)
{
    extern __shared__ char smx[];
    const uint32_t sb = smem_u32(smx);
    int* s_src = (int*)(smx + E_SRC);
    const int tid = threadIdx.x, lane = tid & 31, wid = tid >> 5;
    const int wm = wid & 3, wn = wid >> 2;

    {
        const uint4* s1 = (const uint4*)((const char*)g_wimg + BW_W1MB);
        uint4* d1 = (uint4*)(smx + E_W1B);
        for (int i = tid; i < 1152; i += 512) d1[i] = s1[i];
    }

    int tile = blockIdx.x;
    if (tile < nTiles) {
        issue_gather(smx, 0, tile, E, tid, edge_feats);
        if (tid < 128) {
            int e = tile * 128 + tid;
            int s = (e < E) ? g_src[e] : -1;
            s_src[tid] = s;
            if (s >= 0) red_add_f(g_degf + s, 1.0f);
        }
    }
    CP_COMMIT();

    int b = 0;
    for (; tile < nTiles; tile += gridDim.x, b ^= 1) {
        CP_WAIT0();
        __syncthreads();     // staging + P[b] + s_src[b] ready; prev tile done

        // convert fp32 ef staging -> fp16 X (stride 144)
        for (int t = tid; t < 1024; t += 512) {
            int row = t >> 3, q = t & 7;
            const float4* sp = (const float4*)(smx + E_EF + row * 256 + q * 32);
            float4 v0 = sp[0], v1 = sp[1];
            *(uint4*)(smx + E_X + row * 144 + q * 16) = make_uint4(
                packh2(__float2half_rn(v0.x), __float2half_rn(v0.y)),
                packh2(__float2half_rn(v0.z), __float2half_rn(v0.w)),
                packh2(__float2half_rn(v1.x), __float2half_rn(v1.y)),
                packh2(__float2half_rn(v1.z), __float2half_rn(v1.w)));
        }
        __syncthreads();     // staging consumed, X built

        int nextTile = tile + gridDim.x;
        if (nextTile < nTiles) {
            issue_gather(smx, b ^ 1, nextTile, E, tid, edge_feats);
            if (tid < 128) {
                int e = nextTile * 128 + tid;
                int s = (e < E) ? g_src[e] : -1;
                s_src[(b ^ 1) * 128 + tid] = s;
                if (s >= 0) red_add_f(g_degf + s, 1.0f);
            }
        }
        CP_COMMIT();

        // GEMM1: K=64, 1-term (ef @ W1b)
        float c[2][4][4];
        #pragma unroll
        for (int i = 0; i < 2; ++i)
            #pragma unroll
            for (int j = 0; j < 4; ++j)
                #pragma unroll
                for (int r = 0; r < 4; ++r) c[i][j][r] = 0.f;
        #pragma unroll
        for (int k = 0; k < 4; ++k)
            gemm_step1<144, 144>(c, sb + E_X, sb + E_W1B, k * 32, k * 32, wm, wn, lane);

        // epilogue: H = lrelu(c + P[b]) in fp32, scatter-add to g_agg
        {
            const int q = lane & 3;
            const int Lb = wn * 32 + q * 8;
            char* pbuf = smx + (b ? E_P1 : E_P0);
            const int* sp = s_src + b * 128;
            #pragma unroll
            for (int mt = 0; mt < 2; ++mt) {
                int r = wm * 32 + mt * 16 + (lane >> 2);
                int s0 = sp[r], s1 = sp[r + 8];
                uint4 pa = *(uint4*)(pbuf + r * 272 + Lb * 2);
                uint4 pbv = *(uint4*)(pbuf + (r + 8) * 272 + Lb * 2);
                if (s0 >= 0) {
                    float2 a0 = unp2(pa.x), a1 = unp2(pa.y), a2 = unp2(pa.z), a3 = unp2(pa.w);
                    float* p = g_agg + (size_t)s0 * 128 + Lb;
                    red_add_v4(p,
                        lrelu(c[mt][0][0] + a0.x), lrelu(c[mt][0][1] + a0.y),
                        lrelu(c[mt][1][0] + a1.x), lrelu(c[mt][1][1] + a1.y));
                    red_add_v4(p + 4,
                        lrelu(c[mt][2][0] + a2.x), lrelu(c[mt][2][1] + a2.y),
                        lrelu(c[mt][3][0] + a3.x), lrelu(c[mt][3][1] + a3.y));
                }
                if (s1 >= 0) {
                    float2 b0 = unp2(pbv.x), b1 = unp2(pbv.y), b2 = unp2(pbv.z), b3 = unp2(pbv.w);
                    float* p = g_agg + (size_t)s1 * 128 + Lb;
                    red_add_v4(p,
                        lrelu(c[mt][0][2] + b0.x), lrelu(c[mt][0][3] + b0.y),
                        lrelu(c[mt][1][2] + b1.x), lrelu(c[mt][1][3] + b1.y));
                    red_add_v4(p + 4,
                        lrelu(c[mt][2][2] + b2.x), lrelu(c[mt][2][3] + b2.y),
                        lrelu(c[mt][3][2] + b3.x), lrelu(c[mt][3][3] + b3.y));
                }
            }
        }
    }
}

// ---------------- persistent node kernel smem layout (bytes) ----------------
#define P_W1  0        // W1U hi (k>=128 rows = Wc), stride 528, 67584
#define P_W2H 67584
#define P_W2L 102400
#define P_XH  137216
#define P_XL  172032
#define P_SB1 206848
#define P_SB2 207360
#define P_VC  207872
#define P_DEG 208384
#define P_DYN 208896

__global__ __launch_bounds__(512, 1)
void node_mma_kernel(const float* __restrict__ b1g, const float* __restrict__ b2g,
                     float* __restrict__ out, int N, int nTiles)
{
    extern __shared__ char smx[];
    const uint32_t sb = smem_u32(smx);
    float* sb1  = (float*)(smx + P_SB1);
    float* sb2  = (float*)(smx + P_SB2);
    float* svc  = (float*)(smx + P_VC);
    float* sdeg = (float*)(smx + P_DEG);
    const int tid = threadIdx.x, lane = tid & 31, wid = tid >> 5;
    const int wm = wid & 3, wn = wid >> 2;

    if (tid < 128)      sb1[tid] = b1g[tid];
    else if (tid < 256) sb2[tid - 128] = b2g[tid - 128];
    else if (tid < 384) svc[tid - 256] = g_vc[tid - 256];
    {
        const uint4* s1 = (const uint4*)((const char*)g_wimg + BW_W1U);
        uint4* d1 = (uint4*)(smx + P_W1);
        for (int i = tid; i < 4224; i += 512) d1[i] = s1[i];
        const uint4* s2 = (const uint4*)((const char*)g_wimg + BW_W2U);
        uint4* d2 = (uint4*)(smx + P_W2H);
        for (int i = tid; i < 4352; i += 512) d2[i] = s2[i];
    }

    for (int tile = blockIdx.x; tile < nTiles; tile += gridDim.x) {
        const int n0 = tile * 128;
        __syncthreads();

        for (int t = tid; t < 128 * 32; t += 512) {
            int row = t >> 5, ch = t & 31;
            int n = n0 + row; if (n >= N) n = N - 1;
            if (ch < 16)
                *(uint4*)(smx + P_XH + row * 272 + ch * 16) = ((const uint4*)(g_nfh + (size_t)n * 128))[ch];
            else
                *(uint4*)(smx + P_XL + row * 272 + (ch - 16) * 16) = ((const uint4*)(g_nfl + (size_t)n * 128))[ch - 16];
        }
        if (tid < 128) {
            int n = n0 + tid;
            sdeg[tid] = (n < N) ? g_degf[n] : 0.f;
        }
        __syncthreads();

        float c[2][4][4];
        #pragma unroll
        for (int i = 0; i < 2; ++i)
            #pragma unroll
            for (int j = 0; j < 4; ++j)
                #pragma unroll
                for (int r = 0; r < 4; ++r) c[i][j][r] = 0.f;
        #pragma unroll
        for (int k = 0; k < 8; ++k)
            gemm_stepA2<272, 528>(c, sb + P_XH, sb + P_XL, sb + P_W1,
                                  k * 32, k * 32, wm, wn, lane);
        __syncthreads();

        // chunk1: aggH (fp32) -> hi/lo, B rows hold Wc at k 128..255
        for (int t = tid; t < 128 * 16; t += 512) {
            int row = t >> 4, ch = t & 15;
            int n = n0 + row; if (n >= N) n = N - 1;
            const float4* bp = (const float4*)(g_agg + (size_t)n * 128 + ch * 8);
            uint4 hi, lo;
            splitpack8(bp[0], bp[1], hi, lo);
            *(uint4*)(smx + P_XH + row * 272 + ch * 16) = hi;
            *(uint4*)(smx + P_XL + row * 272 + ch * 16) = lo;
        }
        __syncthreads();
        #pragma unroll
        for (int k = 0; k < 8; ++k)
            gemm_stepA2<272, 528>(c, sb + P_XH, sb + P_XL, sb + P_W1,
                                  k * 32, 256 + k * 32, wm, wn, lane);
        __syncthreads();

        // epilogue1: bias + deg*vc + lrelu -> H hi/lo (overlays X region)
        #pragma unroll
        for (int mt = 0; mt < 2; ++mt)
            #pragma unroll
            for (int nt = 0; nt < 4; ++nt) {
                int r0  = wm * 32 + mt * 16 + (lane >> 2);
                int col = wn * 32 + nt * 8 + (lane & 3) * 2;
                float dA = sdeg[r0], dB = sdeg[r0 + 8];
                float vca = svc[col], vcb = svc[col + 1];
                float ba = sb1[col], bb = sb1[col + 1];
                float f0 = lrelu(c[mt][nt][0] + ba + dA * vca), f1 = lrelu(c[mt][nt][1] + bb + dA * vcb);
                float f2 = lrelu(c[mt][nt][2] + ba + dB * vca), f3 = lrelu(c[mt][nt][3] + bb + dB * vcb);
                __half h0 = __float2half_rn(f0), h1 = __float2half_rn(f1);
                __half h2 = __float2half_rn(f2), h3 = __float2half_rn(f3);
                *(uint32_t*)(smx + P_XH + r0 * 272 + col * 2)       = packh2(h0, h1);
                *(uint32_t*)(smx + P_XH + (r0 + 8) * 272 + col * 2) = packh2(h2, h3);
                *(uint32_t*)(smx + P_XL + r0 * 272 + col * 2) =
                    packh2(__float2half_rn(f0 - __half2float(h0)), __float2half_rn(f1 - __half2float(h1)));
                *(uint32_t*)(smx + P_XL + (r0 + 8) * 272 + col * 2) =
                    packh2(__float2half_rn(f2 - __half2float(h2)), __float2half_rn(f3 - __half2float(h3)));
            }
        __syncthreads();

        // GEMM2: K=128, 3-term
        #pragma unroll
        for (int i = 0; i < 2; ++i)
            #pragma unroll
            for (int j = 0; j < 4; ++j)
                #pragma unroll
                for (int r = 0; r < 4; ++r) c[i][j][r] = 0.f;
        #pragma unroll
        for (int k = 0; k < 8; ++k)
            gemm_step3<272, 272>(c, sb + P_XH, sb + P_XL, sb + P_W2H, sb + P_W2L,
                                 k * 32, k * 32, wm, wn, lane);

        {
            const int q = lane & 3;
            const int Lb = wn * 32 + q * 8;
            float c0 = sb2[Lb],     c1 = sb2[Lb + 1], c2 = sb2[Lb + 2], c3 = sb2[Lb + 3];
            float c4 = sb2[Lb + 4], c5 = sb2[Lb + 5], c6 = sb2[Lb + 6], c7 = sb2[Lb + 7];
            #pragma unroll
            for (int mt = 0; mt < 2; ++mt) {
                int r = wm * 32 + mt * 16 + (lane >> 2);
                int nA = n0 + r, nB = n0 + r + 8;
                if (nA < N) {
                    float4* p = (float4*)(out + (size_t)nA * 128 + Lb);
                    p[0] = make_float4(c[mt][0][0] + c0, c[mt][0][1] + c1, c[mt][1][0] + c2, c[mt][1][1] + c3);
                    p[1] = make_float4(c[mt][2][0] + c4, c[mt][2][1] + c5, c[mt][3][0] + c6, c[mt][3][1] + c7);
                }
                if (nB < N) {
                    float4* p = (float4*)(out + (size_t)nB * 128 + Lb);
                    p[0] = make_float4(c[mt][0][2] + c0, c[mt][0][3] + c1, c[mt][1][2] + c2, c[mt][1][3] + c3);
                    p[1] = make_float4(c[mt][2][2] + c4, c[mt][2][3] + c5, c[mt][3][2] + c6, c[mt][3][3] + c7);
                }
            }
        }
    }
}

// ---------------------------------------------------------------------------

extern "C" void kernel_launch(void* const* d_in, const int* in_sizes, int n_in,
                              void* d_out, int out_size)
{
    const float* node_feats = (const float*)d_in[0];
    const float* edge_feats = (const float*)d_in[1];
    const float* msg_w1     = (const float*)d_in[2];
    const float* msg_b1     = (const float*)d_in[3];
    const float* msg_w2     = (const float*)d_in[4];
    const float* msg_b2     = (const float*)d_in[5];
    const float* upd_w1     = (const float*)d_in[6];
    const float* upd_b1     = (const float*)d_in[7];
    const float* upd_w2     = (const float*)d_in[8];
    const float* upd_b2     = (const float*)d_in[9];
    const void*  edge_index = d_in[10];

    const int N = in_sizes[0] / 128;   // 50000
    const int E = in_sizes[1] / 64;    // 800000
    const int nTiles  = (E + 127) / 128;
    const int nNTiles = (N + 127) / 128;

    cudaFuncSetAttribute(pmat_kernel,     cudaFuncAttributeMaxDynamicSharedMemorySize, Q_DYN);
    cudaFuncSetAttribute(edge_mma_kernel, cudaFuncAttributeMaxDynamicSharedMemorySize, E_DYN);
    cudaFuncSetAttribute(node_mma_kernel, cudaFuncAttributeMaxDynamicSharedMemorySize, P_DYN);

    prep_kernel<<<1024, 256>>>(node_feats, msg_w1, msg_w2, msg_b2,
                               upd_w1, upd_w2, edge_index, N, E);

    pmat_kernel<<<148, 512, Q_DYN>>>(msg_b1, N, nNTiles);

    edge_mma_kernel<<<148, 512, E_DYN>>>(edge_feats, E, nTiles);

    node_mma_kernel<<<148, 512, P_DYN>>>(upd_b1, upd_b2, (float*)d_out, N, nNTiles);
}